// round 2
// baseline (speedup 1.0000x reference)
#include <cuda_runtime.h>

#define BDIM 4
#define SEQ  2048
#define DM   1024
#define NH   16
#define HD   64
#define BH   (BDIM*NH)     // 64
#define MTOT (BDIM*SEQ)    // 8192
#define ASTRIDE 68         // 64 + 4 pad, keeps float4 alignment + conflict-free LDS

// Static scratch (allocation-free rule): q/k/v in [B,H,S,hd], merged attn out [B,S,D]
__device__ float g_q[BH * SEQ * HD];
__device__ float g_k[BH * SEQ * HD];
__device__ float g_v[BH * SEQ * HD];
__device__ float g_a[MTOT * DM];

// ---------------------------------------------------------------------------
// Tiled fp32 GEMM: C[M,N] = A[M,K] @ B[K,N] + bias
// EPI = 0: plain store to C.  EPI = 1: scatter into g_q/g_k/g_v (QKV split).
// ASRC = 1: read A from g_a instead of the pointer argument.
// ---------------------------------------------------------------------------
template<int M, int N, int K, int EPI, int ASRC>
__global__ __launch_bounds__(256) void gemm_kernel(const float* __restrict__ A,
                                                   const float* __restrict__ B,
                                                   const float* __restrict__ bias,
                                                   float* __restrict__ C)
{
    constexpr int BM = 128, BN = 128, BK = 16;
    __shared__ float As[BK][BM + 4];   // padded: fewer STS conflicts on transpose
    __shared__ float Bs[BK][BN];

    const float* Ap = (ASRC == 1) ? g_a : A;

    const int t  = threadIdx.x;
    const int tx = t & 15;
    const int ty = t >> 4;
    const int row0 = blockIdx.y * BM;
    const int col0 = blockIdx.x * BN;

    float acc[8][8];
    #pragma unroll
    for (int i = 0; i < 8; i++)
        #pragma unroll
        for (int j = 0; j < 8; j++) acc[i][j] = 0.f;

    // A-tile loader: 128 rows x 16 cols = 512 float4; thread t does idx {t, t+256}
    const int arow = t >> 2;      // 0..63 (second load adds 64)
    const int acv  = t & 3;       // float4 column within 16
    // B-tile loader: 16 rows x 128 cols = 512 float4
    const int brow = t >> 5;      // 0..7 (second load adds 8)
    const int bcv  = t & 31;

    for (int k0 = 0; k0 < K; k0 += BK) {
        float4 a0 = *reinterpret_cast<const float4*>(&Ap[(row0 + arow)      * K + k0 + acv * 4]);
        float4 a1 = *reinterpret_cast<const float4*>(&Ap[(row0 + arow + 64) * K + k0 + acv * 4]);
        float4 b0 = *reinterpret_cast<const float4*>(&B [(k0 + brow)     * N + col0 + bcv * 4]);
        float4 b1 = *reinterpret_cast<const float4*>(&B [(k0 + brow + 8) * N + col0 + bcv * 4]);
        __syncthreads();
        As[acv * 4 + 0][arow] = a0.x;  As[acv * 4 + 1][arow] = a0.y;
        As[acv * 4 + 2][arow] = a0.z;  As[acv * 4 + 3][arow] = a0.w;
        As[acv * 4 + 0][arow + 64] = a1.x;  As[acv * 4 + 1][arow + 64] = a1.y;
        As[acv * 4 + 2][arow + 64] = a1.z;  As[acv * 4 + 3][arow + 64] = a1.w;
        *reinterpret_cast<float4*>(&Bs[brow]    [bcv * 4]) = b0;
        *reinterpret_cast<float4*>(&Bs[brow + 8][bcv * 4]) = b1;
        __syncthreads();

        #pragma unroll
        for (int kk = 0; kk < BK; kk++) {
            float4 af0 = *reinterpret_cast<const float4*>(&As[kk][ty * 4]);
            float4 af1 = *reinterpret_cast<const float4*>(&As[kk][64 + ty * 4]);
            float4 bf0 = *reinterpret_cast<const float4*>(&Bs[kk][tx * 4]);
            float4 bf1 = *reinterpret_cast<const float4*>(&Bs[kk][64 + tx * 4]);
            float av[8] = {af0.x, af0.y, af0.z, af0.w, af1.x, af1.y, af1.z, af1.w};
            float bv[8] = {bf0.x, bf0.y, bf0.z, bf0.w, bf1.x, bf1.y, bf1.z, bf1.w};
            #pragma unroll
            for (int i = 0; i < 8; i++)
                #pragma unroll
                for (int j = 0; j < 8; j++)
                    acc[i][j] = fmaf(av[i], bv[j], acc[i][j]);
        }
    }

    #pragma unroll
    for (int i = 0; i < 8; i++) {
        int r = row0 + ((i < 4) ? (ty * 4 + i) : (64 + ty * 4 + (i - 4)));
        #pragma unroll
        for (int j = 0; j < 8; j++) {
            int c = col0 + ((j < 4) ? (tx * 4 + j) : (64 + tx * 4 + (j - 4)));
            float v = acc[i][j] + bias[c];
            if (EPI == 0) {
                C[(size_t)r * N + c] = v;
            } else {
                int which = c >> 10;          // 0:q 1:k 2:v
                int dd    = c & 1023;
                int h     = dd >> 6;
                int d     = dd & 63;
                int b     = r >> 11;
                int s     = r & 2047;
                int dst   = (((b * NH + h) * SEQ) + s) * HD + d;
                if      (which == 0) g_q[dst] = v;
                else if (which == 1) g_k[dst] = v;
                else                 g_v[dst] = v;
            }
        }
    }
}

// ---------------------------------------------------------------------------
// Flash-style causal attention. One CTA = one (b*h, 64-row q tile).
// 8 warps; warp w owns q rows [w*8, w*8+8). Lane owns key cols {lane, lane+32}
// and output dims {lane, lane+32}. Online softmax; causal tile skipping.
// ---------------------------------------------------------------------------
__global__ __launch_bounds__(256) void attn_kernel(const float* __restrict__ amask)
{
    extern __shared__ float smem[];
    float* Qs = smem;                       // 64 * ASTRIDE
    float* Ks = Qs + 64 * ASTRIDE;
    float* Vs = Ks + 64 * ASTRIDE;
    float* Ps = Vs + 64 * ASTRIDE;
    float* Ms = Ps + 64 * ASTRIDE;          // SEQ floats (mask row for this batch)

    const int bh   = blockIdx.y;
    const int qt   = blockIdx.x;
    const int b    = bh >> 4;
    const int h    = bh & 15;
    const int q0   = qt * 64;
    const int t    = threadIdx.x;
    const int warp = t >> 5;
    const int lane = t & 31;

    const float* Qg = g_q + (size_t)bh * SEQ * HD;
    const float* Kg = g_k + (size_t)bh * SEQ * HD;
    const float* Vg = g_v + (size_t)bh * SEQ * HD;

    // Load Q tile (64x64) and the additive mask row
    for (int idx = t; idx < 1024; idx += 256) {
        int r = idx >> 4, d4 = idx & 15;
        *reinterpret_cast<float4*>(&Qs[r * ASTRIDE + d4 * 4]) =
            *reinterpret_cast<const float4*>(&Qg[(q0 + r) * HD + d4 * 4]);
    }
    for (int i = t; i < SEQ; i += 256) Ms[i] = amask[b * SEQ + i];
    __syncthreads();

    float o[8][2];
    float m_i[8], l_i[8];
    #pragma unroll
    for (int rr = 0; rr < 8; rr++) {
        o[rr][0] = 0.f; o[rr][1] = 0.f;
        m_i[rr] = -1e30f; l_i[rr] = 0.f;
    }

    const int ktiles = qt + 1;   // causal: tiles fully above diagonal skipped
    for (int kt = 0; kt < ktiles; kt++) {
        const int k0 = kt * 64;
        __syncthreads();  // previous tile's Vs reads done
        for (int idx = t; idx < 1024; idx += 256) {
            int r = idx >> 4, d4 = idx & 15;
            *reinterpret_cast<float4*>(&Ks[r * ASTRIDE + d4 * 4]) =
                *reinterpret_cast<const float4*>(&Kg[(k0 + r) * HD + d4 * 4]);
            *reinterpret_cast<float4*>(&Vs[r * ASTRIDE + d4 * 4]) =
                *reinterpret_cast<const float4*>(&Vg[(k0 + r) * HD + d4 * 4]);
        }
        __syncthreads();

        // S = Q K^T, online softmax, store P to smem
        #pragma unroll
        for (int rr = 0; rr < 8; rr++) {
            const int r = warp * 8 + rr;
            float acc0 = 0.f, acc1 = 0.f;
            #pragma unroll
            for (int d4 = 0; d4 < 16; d4++) {
                float4 q4 = *reinterpret_cast<const float4*>(&Qs[r * ASTRIDE + d4 * 4]);
                float4 ka = *reinterpret_cast<const float4*>(&Ks[lane * ASTRIDE + d4 * 4]);
                float4 kb = *reinterpret_cast<const float4*>(&Ks[(lane + 32) * ASTRIDE + d4 * 4]);
                acc0 = fmaf(q4.x, ka.x, fmaf(q4.y, ka.y, fmaf(q4.z, ka.z, fmaf(q4.w, ka.w, acc0))));
                acc1 = fmaf(q4.x, kb.x, fmaf(q4.y, kb.y, fmaf(q4.z, kb.z, fmaf(q4.w, kb.w, acc1))));
            }
            const int qi = q0 + r;
            const int k1 = k0 + lane, k2 = k0 + lane + 32;
            float s0 = (k1 <= qi) ? (acc0 * 0.125f + Ms[k1]) : (-10000.f + Ms[k1]);
            float s1 = (k2 <= qi) ? (acc1 * 0.125f + Ms[k2]) : (-10000.f + Ms[k2]);

            float mt = fmaxf(s0, s1);
            #pragma unroll
            for (int off = 16; off > 0; off >>= 1)
                mt = fmaxf(mt, __shfl_xor_sync(0xffffffffu, mt, off));
            float m_new = fmaxf(m_i[rr], mt);
            float alpha = __expf(m_i[rr] - m_new);
            m_i[rr] = m_new;
            float p0 = __expf(s0 - m_new);
            float p1 = __expf(s1 - m_new);
            float ps = p0 + p1;
            #pragma unroll
            for (int off = 16; off > 0; off >>= 1)
                ps += __shfl_xor_sync(0xffffffffu, ps, off);
            l_i[rr] = l_i[rr] * alpha + ps;
            o[rr][0] *= alpha;
            o[rr][1] *= alpha;
            Ps[r * ASTRIDE + lane]      = p0;
            Ps[r * ASTRIDE + lane + 32] = p1;
        }
        __syncwarp();

        // O += P @ V  (k outer so V loads are reused across the 8 rows)
        #pragma unroll 8
        for (int k = 0; k < 64; k++) {
            float v0 = Vs[k * ASTRIDE + lane];
            float v1 = Vs[k * ASTRIDE + lane + 32];
            #pragma unroll
            for (int rr = 0; rr < 8; rr++) {
                float p = Ps[(warp * 8 + rr) * ASTRIDE + k];
                o[rr][0] = fmaf(p, v0, o[rr][0]);
                o[rr][1] = fmaf(p, v1, o[rr][1]);
            }
        }
        __syncwarp();
    }

    // Epilogue: normalize and write merged-head layout [B,S,D]
    #pragma unroll
    for (int rr = 0; rr < 8; rr++) {
        float inv = 1.f / l_i[rr];
        int s = q0 + warp * 8 + rr;
        size_t base = ((size_t)(b * SEQ + s)) * DM + h * HD;
        g_a[base + lane]      = o[rr][0] * inv;
        g_a[base + lane + 32] = o[rr][1] * inv;
    }
}

// ---------------------------------------------------------------------------
extern "C" void kernel_launch(void* const* d_in, const int* in_sizes, int n_in,
                              void* d_out, int out_size)
{
    const float* x      = (const float*)d_in[0];
    const float* amask  = (const float*)d_in[1];
    const float* W_attn = (const float*)d_in[2];
    const float* b_attn = (const float*)d_in[3];
    const float* W_proj = (const float*)d_in[4];
    const float* b_proj = (const float*)d_in[5];
    float* out = (float*)d_out;

    // 1) QKV GEMM with head-split scatter epilogue
    dim3 g1(3072 / 128, MTOT / 128);
    gemm_kernel<MTOT, 3072, DM, 1, 0><<<g1, 256>>>(x, W_attn, b_attn, out);

    // 2) Attention
    size_t smem = (size_t)(4 * 64 * ASTRIDE + SEQ) * sizeof(float);  // 77,824 B
    cudaFuncSetAttribute(attn_kernel, cudaFuncAttributeMaxDynamicSharedMemorySize, (int)smem);
    attn_kernel<<<dim3(SEQ / 64, BH), 256, smem>>>(amask);

    // 3) Output projection
    dim3 g2(DM / 128, MTOT / 128);
    gemm_kernel<MTOT, DM, DM, 0, 1><<<g2, 256>>>(nullptr, W_proj, b_proj, out);
}

// round 5
// speedup vs baseline: 1.4493x; 1.4493x over previous
#include <cuda_runtime.h>
#include <cstdint>

#define BDIM 4
#define SEQ  2048
#define DM   1024
#define NH   16
#define HD   64
#define BH   (BDIM*NH)     // 64
#define MTOT (BDIM*SEQ)    // 8192
#define ASTRIDE 68         // attention smem stride

// Static scratch: q/k/v in [B,H,S,hd], merged attn out [B,S,D]
__device__ float g_q[BH * SEQ * HD];
__device__ float g_k[BH * SEQ * HD];
__device__ float g_v[BH * SEQ * HD];
__device__ float g_a[MTOT * DM];

__device__ __forceinline__ float f2tf32(float f) {
    uint32_t u;
    asm("cvt.rna.tf32.f32 %0, %1;" : "=r"(u) : "f"(f));
    return __uint_as_float(u);
}

__device__ __forceinline__ void mma_tf32(float* d, const uint32_t* a, const uint32_t* b) {
    asm volatile(
        "mma.sync.aligned.m16n8k8.row.col.f32.tf32.tf32.f32 "
        "{%0,%1,%2,%3}, {%4,%5,%6,%7}, {%8,%9}, {%0,%1,%2,%3};"
        : "+f"(d[0]), "+f"(d[1]), "+f"(d[2]), "+f"(d[3])
        : "r"(a[0]), "r"(a[1]), "r"(a[2]), "r"(a[3]), "r"(b[0]), "r"(b[1]));
}

// ---------------------------------------------------------------------------
// TF32 tensor-core GEMM: C[M,N] = A[M,K] @ B[K,N] + bias
// EPI=0: plain store. EPI=1: scatter into g_q/g_k/g_v. ASRC=1: A from g_a.
// 256 thr = 8 warps as 2(m) x 4(n); warp tile 64x32; BM=128 BN=128 BK=16.
// ---------------------------------------------------------------------------
template<int M, int N, int K, int EPI, int ASRC>
__global__ __launch_bounds__(256) void gemm_tc(const float* __restrict__ A,
                                               const float* __restrict__ B,
                                               const float* __restrict__ bias,
                                               float* __restrict__ C)
{
    constexpr int BM = 128, BN = 128, BK = 16;
    constexpr int AS = 20;    // As row stride (16 data + 4 pad): g*20+c perm mod 32
    constexpr int BS = 136;   // Bs row stride (128 + 8 pad): c*8+n conflict-free
    __shared__ float As[BM * AS];   // 10 KB
    __shared__ float Bs[BK * BS];   // 8.5 KB

    const float* Ap = (ASRC == 1) ? g_a : A;

    const int t    = threadIdx.x;
    const int warp = t >> 5;
    const int lane = t & 31;
    const int wm   = (warp >> 2) * 64;   // 0 or 64
    const int wn   = (warp & 3) * 32;    // 0,32,64,96
    const int g    = lane >> 2;
    const int c    = lane & 3;
    const int row0 = blockIdx.y * BM;
    const int col0 = blockIdx.x * BN;

    // staging indices
    const int arow = t >> 2;   // 0..63 (+64 second)
    const int acv  = t & 3;
    const int brow = t >> 5;   // 0..7 (+8 second)
    const int bcv  = t & 31;

    float acc[4][4][4];
    #pragma unroll
    for (int i = 0; i < 4; i++)
        #pragma unroll
        for (int j = 0; j < 4; j++)
            #pragma unroll
            for (int q = 0; q < 4; q++) acc[i][j][q] = 0.f;

    for (int k0 = 0; k0 < K; k0 += BK) {
        float4 a0 = *reinterpret_cast<const float4*>(&Ap[(size_t)(row0 + arow)      * K + k0 + acv * 4]);
        float4 a1 = *reinterpret_cast<const float4*>(&Ap[(size_t)(row0 + arow + 64) * K + k0 + acv * 4]);
        float4 b0 = *reinterpret_cast<const float4*>(&B [(size_t)(k0 + brow)     * N + col0 + bcv * 4]);
        float4 b1 = *reinterpret_cast<const float4*>(&B [(size_t)(k0 + brow + 8) * N + col0 + bcv * 4]);
        __syncthreads();
        float4 t0 = make_float4(f2tf32(a0.x), f2tf32(a0.y), f2tf32(a0.z), f2tf32(a0.w));
        float4 t1 = make_float4(f2tf32(a1.x), f2tf32(a1.y), f2tf32(a1.z), f2tf32(a1.w));
        float4 t2 = make_float4(f2tf32(b0.x), f2tf32(b0.y), f2tf32(b0.z), f2tf32(b0.w));
        float4 t3 = make_float4(f2tf32(b1.x), f2tf32(b1.y), f2tf32(b1.z), f2tf32(b1.w));
        *reinterpret_cast<float4*>(&As[(arow)      * AS + acv * 4]) = t0;
        *reinterpret_cast<float4*>(&As[(arow + 64) * AS + acv * 4]) = t1;
        *reinterpret_cast<float4*>(&Bs[(brow)     * BS + bcv * 4]) = t2;
        *reinterpret_cast<float4*>(&Bs[(brow + 8) * BS + bcv * 4]) = t3;
        __syncthreads();

        #pragma unroll
        for (int s = 0; s < 2; s++) {
            const int kk = s * 8 + c;
            uint32_t af[4][4], bf[4][2];
            #pragma unroll
            for (int i = 0; i < 4; i++) {
                const int r = wm + i * 16 + g;
                af[i][0] = __float_as_uint(As[r * AS + kk]);
                af[i][1] = __float_as_uint(As[(r + 8) * AS + kk]);
                af[i][2] = __float_as_uint(As[r * AS + kk + 4]);
                af[i][3] = __float_as_uint(As[(r + 8) * AS + kk + 4]);
            }
            #pragma unroll
            for (int j = 0; j < 4; j++) {
                const int col = wn + j * 8 + g;
                bf[j][0] = __float_as_uint(Bs[kk * BS + col]);
                bf[j][1] = __float_as_uint(Bs[(kk + 4) * BS + col]);
            }
            #pragma unroll
            for (int i = 0; i < 4; i++)
                #pragma unroll
                for (int j = 0; j < 4; j++)
                    mma_tf32(acc[i][j], af[i], bf[j]);
        }
    }

    // Epilogue. C frag: c0 (g, 2c), c1 (g, 2c+1), c2 (g+8, 2c), c3 (g+8, 2c+1)
    #pragma unroll
    for (int i = 0; i < 4; i++) {
        const int r_lo = row0 + wm + i * 16 + g;
        #pragma unroll
        for (int j = 0; j < 4; j++) {
            const int cb = col0 + wn + j * 8 + c * 2;
            float v00 = acc[i][j][0] + bias[cb];
            float v01 = acc[i][j][1] + bias[cb + 1];
            float v10 = acc[i][j][2] + bias[cb];
            float v11 = acc[i][j][3] + bias[cb + 1];
            if (EPI == 0) {
                *reinterpret_cast<float2*>(&C[(size_t)r_lo * N + cb])       = make_float2(v00, v01);
                *reinterpret_cast<float2*>(&C[(size_t)(r_lo + 8) * N + cb]) = make_float2(v10, v11);
            } else {
                const int which = cb >> 10;        // 0:q 1:k 2:v
                const int dd    = cb & 1023;
                const int h     = dd >> 6;
                const int d     = dd & 63;
                float* dst = (which == 0) ? g_q : (which == 1) ? g_k : g_v;
                #pragma unroll
                for (int rr = 0; rr < 2; rr++) {
                    const int r = r_lo + rr * 8;
                    const int b = r >> 11;
                    const int s = r & 2047;
                    const size_t di = (((size_t)(b * NH + h) * SEQ) + s) * HD + d;
                    *reinterpret_cast<float2*>(&dst[di]) =
                        make_float2(rr ? v10 : v00, rr ? v11 : v01);
                }
            }
        }
    }
}

// ---------------------------------------------------------------------------
// Flash-style causal attention (unchanged from R1). One CTA = (b*h, 64 q rows).
// ---------------------------------------------------------------------------
__global__ __launch_bounds__(256) void attn_kernel(const float* __restrict__ amask)
{
    extern __shared__ float smem[];
    float* Qs = smem;
    float* Ks = Qs + 64 * ASTRIDE;
    float* Vs = Ks + 64 * ASTRIDE;
    float* Ps = Vs + 64 * ASTRIDE;
    float* Ms = Ps + 64 * ASTRIDE;

    const int bh   = blockIdx.y;
    const int qt   = blockIdx.x;
    const int b    = bh >> 4;
    const int h    = bh & 15;
    const int q0   = qt * 64;
    const int t    = threadIdx.x;
    const int warp = t >> 5;
    const int lane = t & 31;

    const float* Qg = g_q + (size_t)bh * SEQ * HD;
    const float* Kg = g_k + (size_t)bh * SEQ * HD;
    const float* Vg = g_v + (size_t)bh * SEQ * HD;

    for (int idx = t; idx < 1024; idx += 256) {
        int r = idx >> 4, d4 = idx & 15;
        *reinterpret_cast<float4*>(&Qs[r * ASTRIDE + d4 * 4]) =
            *reinterpret_cast<const float4*>(&Qg[(q0 + r) * HD + d4 * 4]);
    }
    for (int i = t; i < SEQ; i += 256) Ms[i] = amask[b * SEQ + i];
    __syncthreads();

    float o[8][2];
    float m_i[8], l_i[8];
    #pragma unroll
    for (int rr = 0; rr < 8; rr++) {
        o[rr][0] = 0.f; o[rr][1] = 0.f;
        m_i[rr] = -1e30f; l_i[rr] = 0.f;
    }

    const int ktiles = qt + 1;
    for (int kt = 0; kt < ktiles; kt++) {
        const int k0 = kt * 64;
        __syncthreads();
        for (int idx = t; idx < 1024; idx += 256) {
            int r = idx >> 4, d4 = idx & 15;
            *reinterpret_cast<float4*>(&Ks[r * ASTRIDE + d4 * 4]) =
                *reinterpret_cast<const float4*>(&Kg[(k0 + r) * HD + d4 * 4]);
            *reinterpret_cast<float4*>(&Vs[r * ASTRIDE + d4 * 4]) =
                *reinterpret_cast<const float4*>(&Vg[(k0 + r) * HD + d4 * 4]);
        }
        __syncthreads();

        #pragma unroll
        for (int rr = 0; rr < 8; rr++) {
            const int r = warp * 8 + rr;
            float acc0 = 0.f, acc1 = 0.f;
            #pragma unroll
            for (int d4 = 0; d4 < 16; d4++) {
                float4 q4 = *reinterpret_cast<const float4*>(&Qs[r * ASTRIDE + d4 * 4]);
                float4 ka = *reinterpret_cast<const float4*>(&Ks[lane * ASTRIDE + d4 * 4]);
                float4 kb = *reinterpret_cast<const float4*>(&Ks[(lane + 32) * ASTRIDE + d4 * 4]);
                acc0 = fmaf(q4.x, ka.x, fmaf(q4.y, ka.y, fmaf(q4.z, ka.z, fmaf(q4.w, ka.w, acc0))));
                acc1 = fmaf(q4.x, kb.x, fmaf(q4.y, kb.y, fmaf(q4.z, kb.z, fmaf(q4.w, kb.w, acc1))));
            }
            const int qi = q0 + r;
            const int k1 = k0 + lane, k2 = k0 + lane + 32;
            float s0 = (k1 <= qi) ? (acc0 * 0.125f + Ms[k1]) : (-10000.f + Ms[k1]);
            float s1 = (k2 <= qi) ? (acc1 * 0.125f + Ms[k2]) : (-10000.f + Ms[k2]);

            float mt = fmaxf(s0, s1);
            #pragma unroll
            for (int off = 16; off > 0; off >>= 1)
                mt = fmaxf(mt, __shfl_xor_sync(0xffffffffu, mt, off));
            float m_new = fmaxf(m_i[rr], mt);
            float alpha = __expf(m_i[rr] - m_new);
            m_i[rr] = m_new;
            float p0 = __expf(s0 - m_new);
            float p1 = __expf(s1 - m_new);
            float ps = p0 + p1;
            #pragma unroll
            for (int off = 16; off > 0; off >>= 1)
                ps += __shfl_xor_sync(0xffffffffu, ps, off);
            l_i[rr] = l_i[rr] * alpha + ps;
            o[rr][0] *= alpha;
            o[rr][1] *= alpha;
            Ps[r * ASTRIDE + lane]      = p0;
            Ps[r * ASTRIDE + lane + 32] = p1;
        }
        __syncwarp();

        #pragma unroll 8
        for (int k = 0; k < 64; k++) {
            float v0 = Vs[k * ASTRIDE + lane];
            float v1 = Vs[k * ASTRIDE + lane + 32];
            #pragma unroll
            for (int rr = 0; rr < 8; rr++) {
                float p = Ps[(warp * 8 + rr) * ASTRIDE + k];
                o[rr][0] = fmaf(p, v0, o[rr][0]);
                o[rr][1] = fmaf(p, v1, o[rr][1]);
            }
        }
        __syncwarp();
    }

    #pragma unroll
    for (int rr = 0; rr < 8; rr++) {
        float inv = 1.f / l_i[rr];
        int s = q0 + warp * 8 + rr;
        size_t base = ((size_t)(b * SEQ + s)) * DM + h * HD;
        g_a[base + lane]      = o[rr][0] * inv;
        g_a[base + lane + 32] = o[rr][1] * inv;
    }
}

// ---------------------------------------------------------------------------
extern "C" void kernel_launch(void* const* d_in, const int* in_sizes, int n_in,
                              void* d_out, int out_size)
{
    const float* x      = (const float*)d_in[0];
    const float* amask  = (const float*)d_in[1];
    const float* W_attn = (const float*)d_in[2];
    const float* b_attn = (const float*)d_in[3];
    const float* W_proj = (const float*)d_in[4];
    const float* b_proj = (const float*)d_in[5];
    float* out = (float*)d_out;

    // 1) QKV GEMM (tf32 tensor cores) with head-split scatter epilogue
    dim3 g1(3072 / 128, MTOT / 128);
    gemm_tc<MTOT, 3072, DM, 1, 0><<<g1, 256>>>(x, W_attn, b_attn, out);

    // 2) Attention
    size_t smem = (size_t)(4 * 64 * ASTRIDE + SEQ) * sizeof(float);
    cudaFuncSetAttribute(attn_kernel, cudaFuncAttributeMaxDynamicSharedMemorySize, (int)smem);
    attn_kernel<<<dim3(SEQ / 64, BH), 256, smem>>>(amask);

    // 3) Output projection (tf32 tensor cores)
    dim3 g2(DM / 128, MTOT / 128);
    gemm_tc<MTOT, DM, DM, 0, 1><<<g2, 256>>>(nullptr, W_proj, b_proj, out);
}

// round 8
// speedup vs baseline: 2.1246x; 1.4659x over previous
#include <cuda_runtime.h>
#include <cstdint>

#define BDIM 4
#define SEQ  2048
#define DM   1024
#define NH   16
#define HD   64
#define BH   (BDIM*NH)     // 64
#define MTOT (BDIM*SEQ)    // 8192

// Static scratch: q/k/v in [B,H,S,hd], merged attn out [B,S,D]
__device__ float g_q[BH * SEQ * HD];
__device__ float g_k[BH * SEQ * HD];
__device__ float g_v[BH * SEQ * HD];
__device__ float g_a[MTOT * DM];

__device__ __forceinline__ float f2tf32(float f) {
    uint32_t u;
    asm("cvt.rna.tf32.f32 %0, %1;" : "=r"(u) : "f"(f));
    return __uint_as_float(u);
}

// split x = hi + lo (both tf32-representable), for 3xTF32 compensation
__device__ __forceinline__ void splitf(float x, uint32_t& h, uint32_t& l) {
    asm("cvt.rna.tf32.f32 %0, %1;" : "=r"(h) : "f"(x));
    float r = x - __uint_as_float(h);
    asm("cvt.rna.tf32.f32 %0, %1;" : "=r"(l) : "f"(r));
}

__device__ __forceinline__ void mma_tf32(float* d, const uint32_t* a, const uint32_t* b) {
    asm volatile(
        "mma.sync.aligned.m16n8k8.row.col.f32.tf32.tf32.f32 "
        "{%0,%1,%2,%3}, {%4,%5,%6,%7}, {%8,%9}, {%0,%1,%2,%3};"
        : "+f"(d[0]), "+f"(d[1]), "+f"(d[2]), "+f"(d[3])
        : "r"(a[0]), "r"(a[1]), "r"(a[2]), "r"(a[3]), "r"(b[0]), "r"(b[1]));
}

// ---------------------------------------------------------------------------
// TF32 tensor-core GEMM (unchanged from R2)
// ---------------------------------------------------------------------------
template<int M, int N, int K, int EPI, int ASRC>
__global__ __launch_bounds__(256) void gemm_tc(const float* __restrict__ A,
                                               const float* __restrict__ B,
                                               const float* __restrict__ bias,
                                               float* __restrict__ C)
{
    constexpr int BM = 128, BN = 128, BK = 16;
    constexpr int AS = 20;
    constexpr int BS = 136;
    __shared__ float As[BM * AS];
    __shared__ float Bs[BK * BS];

    const float* Ap = (ASRC == 1) ? g_a : A;

    const int t    = threadIdx.x;
    const int warp = t >> 5;
    const int lane = t & 31;
    const int wm   = (warp >> 2) * 64;
    const int wn   = (warp & 3) * 32;
    const int g    = lane >> 2;
    const int c    = lane & 3;
    const int row0 = blockIdx.y * BM;
    const int col0 = blockIdx.x * BN;

    const int arow = t >> 2;
    const int acv  = t & 3;
    const int brow = t >> 5;
    const int bcv  = t & 31;

    float acc[4][4][4];
    #pragma unroll
    for (int i = 0; i < 4; i++)
        #pragma unroll
        for (int j = 0; j < 4; j++)
            #pragma unroll
            for (int q = 0; q < 4; q++) acc[i][j][q] = 0.f;

    for (int k0 = 0; k0 < K; k0 += BK) {
        float4 a0 = *reinterpret_cast<const float4*>(&Ap[(size_t)(row0 + arow)      * K + k0 + acv * 4]);
        float4 a1 = *reinterpret_cast<const float4*>(&Ap[(size_t)(row0 + arow + 64) * K + k0 + acv * 4]);
        float4 b0 = *reinterpret_cast<const float4*>(&B [(size_t)(k0 + brow)     * N + col0 + bcv * 4]);
        float4 b1 = *reinterpret_cast<const float4*>(&B [(size_t)(k0 + brow + 8) * N + col0 + bcv * 4]);
        __syncthreads();
        float4 t0 = make_float4(f2tf32(a0.x), f2tf32(a0.y), f2tf32(a0.z), f2tf32(a0.w));
        float4 t1 = make_float4(f2tf32(a1.x), f2tf32(a1.y), f2tf32(a1.z), f2tf32(a1.w));
        float4 t2 = make_float4(f2tf32(b0.x), f2tf32(b0.y), f2tf32(b0.z), f2tf32(b0.w));
        float4 t3 = make_float4(f2tf32(b1.x), f2tf32(b1.y), f2tf32(b1.z), f2tf32(b1.w));
        *reinterpret_cast<float4*>(&As[(arow)      * AS + acv * 4]) = t0;
        *reinterpret_cast<float4*>(&As[(arow + 64) * AS + acv * 4]) = t1;
        *reinterpret_cast<float4*>(&Bs[(brow)     * BS + bcv * 4]) = t2;
        *reinterpret_cast<float4*>(&Bs[(brow + 8) * BS + bcv * 4]) = t3;
        __syncthreads();

        #pragma unroll
        for (int s = 0; s < 2; s++) {
            const int kk = s * 8 + c;
            uint32_t af[4][4], bf[4][2];
            #pragma unroll
            for (int i = 0; i < 4; i++) {
                const int r = wm + i * 16 + g;
                af[i][0] = __float_as_uint(As[r * AS + kk]);
                af[i][1] = __float_as_uint(As[(r + 8) * AS + kk]);
                af[i][2] = __float_as_uint(As[r * AS + kk + 4]);
                af[i][3] = __float_as_uint(As[(r + 8) * AS + kk + 4]);
            }
            #pragma unroll
            for (int j = 0; j < 4; j++) {
                const int col = wn + j * 8 + g;
                bf[j][0] = __float_as_uint(Bs[kk * BS + col]);
                bf[j][1] = __float_as_uint(Bs[(kk + 4) * BS + col]);
            }
            #pragma unroll
            for (int i = 0; i < 4; i++)
                #pragma unroll
                for (int j = 0; j < 4; j++)
                    mma_tf32(acc[i][j], af[i], bf[j]);
        }
    }

    #pragma unroll
    for (int i = 0; i < 4; i++) {
        const int r_lo = row0 + wm + i * 16 + g;
        #pragma unroll
        for (int j = 0; j < 4; j++) {
            const int cb = col0 + wn + j * 8 + c * 2;
            float v00 = acc[i][j][0] + bias[cb];
            float v01 = acc[i][j][1] + bias[cb + 1];
            float v10 = acc[i][j][2] + bias[cb];
            float v11 = acc[i][j][3] + bias[cb + 1];
            if (EPI == 0) {
                *reinterpret_cast<float2*>(&C[(size_t)r_lo * N + cb])       = make_float2(v00, v01);
                *reinterpret_cast<float2*>(&C[(size_t)(r_lo + 8) * N + cb]) = make_float2(v10, v11);
            } else {
                const int which = cb >> 10;
                const int dd    = cb & 1023;
                const int h     = dd >> 6;
                const int d     = dd & 63;
                float* dst = (which == 0) ? g_q : (which == 1) ? g_k : g_v;
                #pragma unroll
                for (int rr = 0; rr < 2; rr++) {
                    const int r = r_lo + rr * 8;
                    const int b = r >> 11;
                    const int s = r & 2047;
                    const size_t di = (((size_t)(b * NH + h) * SEQ) + s) * HD + d;
                    *reinterpret_cast<float2*>(&dst[di]) =
                        make_float2(rr ? v10 : v00, rr ? v11 : v01);
                }
            }
        }
    }
}

// ---------------------------------------------------------------------------
// Tensor-core flash attention, 3xTF32 compensated.
// CTA = (64 q rows, one b*h). 4 warps; warp w owns q rows [w*16, w*16+16).
// S = Q K^T (m16n8k8 over 8 key-tiles x 8 hd-steps), online softmax on
// accumulator frags, P -> smem, O += P V. All frag LDS conflict-free.
// ---------------------------------------------------------------------------
#define QKS 68   // Qs/Ks/Ps row stride (words): bank = 4g+c, conflict-free
#define VST 72   // Vs row stride: bank = 8c+g, conflict-free

__global__ __launch_bounds__(128) void attn_tc(const float* __restrict__ amask)
{
    extern __shared__ float smem[];
    float* Qs = smem;                   // 64*68
    float* Ks = Qs + 64 * QKS;          // 64*68
    float* Vs = Ks + 64 * QKS;          // 64*72  [key][hd]
    float* Ps = Vs + 64 * VST;          // 64*68
    float* Ms = Ps + 64 * QKS;          // SEQ

    const int bh   = blockIdx.y;
    const int qt   = blockIdx.x;
    const int b    = bh >> 4;
    const int h    = bh & 15;
    const int q0   = qt * 64;
    const int t    = threadIdx.x;
    const int warp = t >> 5;
    const int lane = t & 31;
    const int g    = lane >> 2;
    const int c    = lane & 3;
    const int wm   = warp * 16;

    const float* Qg = g_q + (size_t)bh * SEQ * HD;
    const float* Kg = g_k + (size_t)bh * SEQ * HD;
    const float* Vg = g_v + (size_t)bh * SEQ * HD;

    // Load Q tile (64x64) and additive mask row
    for (int idx = t; idx < 1024; idx += 128) {
        int r = idx >> 4, d4 = idx & 15;
        *reinterpret_cast<float4*>(&Qs[r * QKS + d4 * 4]) =
            *reinterpret_cast<const float4*>(&Qg[(q0 + r) * HD + d4 * 4]);
    }
    for (int i = t; i < SEQ; i += 128) Ms[i] = amask[b * SEQ + i];

    const int r0 = q0 + wm + g;      // this thread's two rows
    const int r1 = r0 + 8;

    float oacc[8][4];
    #pragma unroll
    for (int j = 0; j < 8; j++)
        #pragma unroll
        for (int q = 0; q < 4; q++) oacc[j][q] = 0.f;
    float m0 = -1e30f, m1 = -1e30f, l0 = 0.f, l1 = 0.f;

    const int ktiles = qt + 1;
    for (int kt = 0; kt < ktiles; kt++) {
        const int k0 = kt * 64;
        __syncthreads();
        for (int idx = t; idx < 1024; idx += 128) {
            int r = idx >> 4, d4 = idx & 15;
            *reinterpret_cast<float4*>(&Ks[r * QKS + d4 * 4]) =
                *reinterpret_cast<const float4*>(&Kg[(k0 + r) * HD + d4 * 4]);
            *reinterpret_cast<float4*>(&Vs[r * VST + d4 * 4]) =
                *reinterpret_cast<const float4*>(&Vg[(k0 + r) * HD + d4 * 4]);
        }
        __syncthreads();

        // ---- S = Q K^T (3xTF32) ----
        float sacc[8][4];
        #pragma unroll
        for (int j = 0; j < 8; j++)
            #pragma unroll
            for (int q = 0; q < 4; q++) sacc[j][q] = 0.f;

        #pragma unroll
        for (int kk = 0; kk < 8; kk++) {
            uint32_t ah[4], al[4];
            splitf(Qs[(wm + g)     * QKS + kk * 8 + c],     ah[0], al[0]);
            splitf(Qs[(wm + g + 8) * QKS + kk * 8 + c],     ah[1], al[1]);
            splitf(Qs[(wm + g)     * QKS + kk * 8 + c + 4], ah[2], al[2]);
            splitf(Qs[(wm + g + 8) * QKS + kk * 8 + c + 4], ah[3], al[3]);
            #pragma unroll
            for (int j = 0; j < 8; j++) {
                uint32_t bhreg[2], blreg[2];
                splitf(Ks[(j * 8 + g) * QKS + kk * 8 + c],     bhreg[0], blreg[0]);
                splitf(Ks[(j * 8 + g) * QKS + kk * 8 + c + 4], bhreg[1], blreg[1]);
                mma_tf32(sacc[j], ah, bhreg);
                mma_tf32(sacc[j], ah, blreg);
                mma_tf32(sacc[j], al, bhreg);
            }
        }

        // ---- masked online softmax on accumulator frags ----
        #pragma unroll
        for (int j = 0; j < 8; j++) {
            const int col  = k0 + j * 8 + 2 * c;
            const int col1 = col + 1;
            const float msk0 = Ms[col], msk1 = Ms[col1];
            sacc[j][0] = (col  <= r0) ? fmaf(sacc[j][0], 0.125f, msk0) : (-10000.f + msk0);
            sacc[j][1] = (col1 <= r0) ? fmaf(sacc[j][1], 0.125f, msk1) : (-10000.f + msk1);
            sacc[j][2] = (col  <= r1) ? fmaf(sacc[j][2], 0.125f, msk0) : (-10000.f + msk0);
            sacc[j][3] = (col1 <= r1) ? fmaf(sacc[j][3], 0.125f, msk1) : (-10000.f + msk1);
        }
        float mt0 = -1e30f, mt1 = -1e30f;
        #pragma unroll
        for (int j = 0; j < 8; j++) {
            mt0 = fmaxf(mt0, fmaxf(sacc[j][0], sacc[j][1]));
            mt1 = fmaxf(mt1, fmaxf(sacc[j][2], sacc[j][3]));
        }
        mt0 = fmaxf(mt0, __shfl_xor_sync(0xffffffffu, mt0, 1));
        mt0 = fmaxf(mt0, __shfl_xor_sync(0xffffffffu, mt0, 2));
        mt1 = fmaxf(mt1, __shfl_xor_sync(0xffffffffu, mt1, 1));
        mt1 = fmaxf(mt1, __shfl_xor_sync(0xffffffffu, mt1, 2));
        const float mn0 = fmaxf(m0, mt0), mn1 = fmaxf(m1, mt1);
        const float al0 = __expf(m0 - mn0), al1 = __expf(m1 - mn1);
        m0 = mn0; m1 = mn1;

        float ps0 = 0.f, ps1 = 0.f;
        #pragma unroll
        for (int j = 0; j < 8; j++) {
            float p0 = __expf(sacc[j][0] - mn0);
            float p1 = __expf(sacc[j][1] - mn0);
            float p2 = __expf(sacc[j][2] - mn1);
            float p3 = __expf(sacc[j][3] - mn1);
            ps0 += p0 + p1;
            ps1 += p2 + p3;
            *reinterpret_cast<float2*>(&Ps[(wm + g)     * QKS + j * 8 + 2 * c]) = make_float2(p0, p1);
            *reinterpret_cast<float2*>(&Ps[(wm + g + 8) * QKS + j * 8 + 2 * c]) = make_float2(p2, p3);
        }
        ps0 += __shfl_xor_sync(0xffffffffu, ps0, 1);
        ps0 += __shfl_xor_sync(0xffffffffu, ps0, 2);
        ps1 += __shfl_xor_sync(0xffffffffu, ps1, 1);
        ps1 += __shfl_xor_sync(0xffffffffu, ps1, 2);
        l0 = l0 * al0 + ps0;
        l1 = l1 * al1 + ps1;
        #pragma unroll
        for (int j = 0; j < 8; j++) {
            oacc[j][0] *= al0; oacc[j][1] *= al0;
            oacc[j][2] *= al1; oacc[j][3] *= al1;
        }
        __syncwarp();

        // ---- O += P V (3xTF32); P rows warp-local ----
        #pragma unroll
        for (int kk = 0; kk < 8; kk++) {
            uint32_t ph[4], pl[4];
            splitf(Ps[(wm + g)     * QKS + kk * 8 + c],     ph[0], pl[0]);
            splitf(Ps[(wm + g + 8) * QKS + kk * 8 + c],     ph[1], pl[1]);
            splitf(Ps[(wm + g)     * QKS + kk * 8 + c + 4], ph[2], pl[2]);
            splitf(Ps[(wm + g + 8) * QKS + kk * 8 + c + 4], ph[3], pl[3]);
            #pragma unroll
            for (int j = 0; j < 8; j++) {
                uint32_t vh[2], vl[2];
                splitf(Vs[(kk * 8 + c)     * VST + j * 8 + g], vh[0], vl[0]);
                splitf(Vs[(kk * 8 + c + 4) * VST + j * 8 + g], vh[1], vl[1]);
                mma_tf32(oacc[j], ph, vh);
                mma_tf32(oacc[j], ph, vl);
                mma_tf32(oacc[j], pl, vh);
            }
        }
    }

    // Epilogue: normalize, write merged-head layout [B,S,D]
    const float inv0 = 1.f / l0, inv1 = 1.f / l1;
    const size_t base0 = ((size_t)(b * SEQ + r0)) * DM + h * HD;
    const size_t base1 = ((size_t)(b * SEQ + r1)) * DM + h * HD;
    #pragma unroll
    for (int j = 0; j < 8; j++) {
        *reinterpret_cast<float2*>(&g_a[base0 + j * 8 + 2 * c]) =
            make_float2(oacc[j][0] * inv0, oacc[j][1] * inv0);
        *reinterpret_cast<float2*>(&g_a[base1 + j * 8 + 2 * c]) =
            make_float2(oacc[j][2] * inv1, oacc[j][3] * inv1);
    }
}

// ---------------------------------------------------------------------------
extern "C" void kernel_launch(void* const* d_in, const int* in_sizes, int n_in,
                              void* d_out, int out_size)
{
    const float* x      = (const float*)d_in[0];
    const float* amask  = (const float*)d_in[1];
    const float* W_attn = (const float*)d_in[2];
    const float* b_attn = (const float*)d_in[3];
    const float* W_proj = (const float*)d_in[4];
    const float* b_proj = (const float*)d_in[5];
    float* out = (float*)d_out;

    // 1) QKV GEMM (tf32 tensor cores) with head-split scatter epilogue
    dim3 g1(3072 / 128, MTOT / 128);
    gemm_tc<MTOT, 3072, DM, 1, 0><<<g1, 256>>>(x, W_attn, b_attn, out);

    // 2) Tensor-core attention
    size_t smem = (size_t)(64 * (QKS * 3 + VST) + SEQ) * sizeof(float);  // 78,848 B
    cudaFuncSetAttribute(attn_tc, cudaFuncAttributeMaxDynamicSharedMemorySize, (int)smem);
    attn_tc<<<dim3(SEQ / 64, BH), 128, smem>>>(amask);

    // 3) Output projection (tf32 tensor cores)
    dim3 g2(DM / 128, MTOT / 128);
    gemm_tc<MTOT, DM, DM, 0, 1><<<g2, 256>>>(nullptr, W_proj, b_proj, out);
}

// round 10
// speedup vs baseline: 2.6303x; 1.2380x over previous
#include <cuda_runtime.h>
#include <cstdint>

#define BDIM 4
#define SEQ  2048
#define DM   1024
#define NH   16
#define HD   64
#define BH   (BDIM*NH)     // 64
#define MTOT (BDIM*SEQ)    // 8192

// Static scratch: q/k/v in [B,H,S,hd], merged attn out [B,S,D]
__device__ float g_q[BH * SEQ * HD];
__device__ float g_k[BH * SEQ * HD];
__device__ float g_v[BH * SEQ * HD];
__device__ float g_a[MTOT * DM];

__device__ __forceinline__ float f2tf32(float f) {
    uint32_t u;
    asm("cvt.rna.tf32.f32 %0, %1;" : "=r"(u) : "f"(f));
    return __uint_as_float(u);
}

// split x = hi + lo (both tf32-representable)
__device__ __forceinline__ void splitf(float x, uint32_t& h, uint32_t& l) {
    asm("cvt.rna.tf32.f32 %0, %1;" : "=r"(h) : "f"(x));
    float r = x - __uint_as_float(h);
    asm("cvt.rna.tf32.f32 %0, %1;" : "=r"(l) : "f"(r));
}

__device__ __forceinline__ float fexp2(float x) {
    float y;
    asm("ex2.approx.ftz.f32 %0, %1;" : "=f"(y) : "f"(x));
    return y;
}

__device__ __forceinline__ void mma_tf32(float* d, const uint32_t* a, const uint32_t* b) {
    asm volatile(
        "mma.sync.aligned.m16n8k8.row.col.f32.tf32.tf32.f32 "
        "{%0,%1,%2,%3}, {%4,%5,%6,%7}, {%8,%9}, {%0,%1,%2,%3};"
        : "+f"(d[0]), "+f"(d[1]), "+f"(d[2]), "+f"(d[3])
        : "r"(a[0]), "r"(a[1]), "r"(a[2]), "r"(a[3]), "r"(b[0]), "r"(b[1]));
}

// ---------------------------------------------------------------------------
// TF32 tensor-core GEMM (unchanged)
// ---------------------------------------------------------------------------
template<int M, int N, int K, int EPI, int ASRC>
__global__ __launch_bounds__(256) void gemm_tc(const float* __restrict__ A,
                                               const float* __restrict__ B,
                                               const float* __restrict__ bias,
                                               float* __restrict__ C)
{
    constexpr int BM = 128, BN = 128, BK = 16;
    constexpr int AS = 20;
    constexpr int BS = 136;
    __shared__ float As[BM * AS];
    __shared__ float Bs[BK * BS];

    const float* Ap = (ASRC == 1) ? g_a : A;

    const int t    = threadIdx.x;
    const int warp = t >> 5;
    const int lane = t & 31;
    const int wm   = (warp >> 2) * 64;
    const int wn   = (warp & 3) * 32;
    const int g    = lane >> 2;
    const int c    = lane & 3;
    const int row0 = blockIdx.y * BM;
    const int col0 = blockIdx.x * BN;

    const int arow = t >> 2;
    const int acv  = t & 3;
    const int brow = t >> 5;
    const int bcv  = t & 31;

    float acc[4][4][4];
    #pragma unroll
    for (int i = 0; i < 4; i++)
        #pragma unroll
        for (int j = 0; j < 4; j++)
            #pragma unroll
            for (int q = 0; q < 4; q++) acc[i][j][q] = 0.f;

    for (int k0 = 0; k0 < K; k0 += BK) {
        float4 a0 = *reinterpret_cast<const float4*>(&Ap[(size_t)(row0 + arow)      * K + k0 + acv * 4]);
        float4 a1 = *reinterpret_cast<const float4*>(&Ap[(size_t)(row0 + arow + 64) * K + k0 + acv * 4]);
        float4 b0 = *reinterpret_cast<const float4*>(&B [(size_t)(k0 + brow)     * N + col0 + bcv * 4]);
        float4 b1 = *reinterpret_cast<const float4*>(&B [(size_t)(k0 + brow + 8) * N + col0 + bcv * 4]);
        __syncthreads();
        float4 t0 = make_float4(f2tf32(a0.x), f2tf32(a0.y), f2tf32(a0.z), f2tf32(a0.w));
        float4 t1 = make_float4(f2tf32(a1.x), f2tf32(a1.y), f2tf32(a1.z), f2tf32(a1.w));
        float4 t2 = make_float4(f2tf32(b0.x), f2tf32(b0.y), f2tf32(b0.z), f2tf32(b0.w));
        float4 t3 = make_float4(f2tf32(b1.x), f2tf32(b1.y), f2tf32(b1.z), f2tf32(b1.w));
        *reinterpret_cast<float4*>(&As[(arow)      * AS + acv * 4]) = t0;
        *reinterpret_cast<float4*>(&As[(arow + 64) * AS + acv * 4]) = t1;
        *reinterpret_cast<float4*>(&Bs[(brow)     * BS + bcv * 4]) = t2;
        *reinterpret_cast<float4*>(&Bs[(brow + 8) * BS + bcv * 4]) = t3;
        __syncthreads();

        #pragma unroll
        for (int s = 0; s < 2; s++) {
            const int kk = s * 8 + c;
            uint32_t af[4][4], bf[4][2];
            #pragma unroll
            for (int i = 0; i < 4; i++) {
                const int r = wm + i * 16 + g;
                af[i][0] = __float_as_uint(As[r * AS + kk]);
                af[i][1] = __float_as_uint(As[(r + 8) * AS + kk]);
                af[i][2] = __float_as_uint(As[r * AS + kk + 4]);
                af[i][3] = __float_as_uint(As[(r + 8) * AS + kk + 4]);
            }
            #pragma unroll
            for (int j = 0; j < 4; j++) {
                const int col = wn + j * 8 + g;
                bf[j][0] = __float_as_uint(Bs[kk * BS + col]);
                bf[j][1] = __float_as_uint(Bs[(kk + 4) * BS + col]);
            }
            #pragma unroll
            for (int i = 0; i < 4; i++)
                #pragma unroll
                for (int j = 0; j < 4; j++)
                    mma_tf32(acc[i][j], af[i], bf[j]);
        }
    }

    #pragma unroll
    for (int i = 0; i < 4; i++) {
        const int r_lo = row0 + wm + i * 16 + g;
        #pragma unroll
        for (int j = 0; j < 4; j++) {
            const int cb = col0 + wn + j * 8 + c * 2;
            float v00 = acc[i][j][0] + bias[cb];
            float v01 = acc[i][j][1] + bias[cb + 1];
            float v10 = acc[i][j][2] + bias[cb];
            float v11 = acc[i][j][3] + bias[cb + 1];
            if (EPI == 0) {
                *reinterpret_cast<float2*>(&C[(size_t)r_lo * N + cb])       = make_float2(v00, v01);
                *reinterpret_cast<float2*>(&C[(size_t)(r_lo + 8) * N + cb]) = make_float2(v10, v11);
            } else {
                const int which = cb >> 10;
                const int dd    = cb & 1023;
                const int h     = dd >> 6;
                const int d     = dd & 63;
                float* dst = (which == 0) ? g_q : (which == 1) ? g_k : g_v;
                #pragma unroll
                for (int rr = 0; rr < 2; rr++) {
                    const int r = r_lo + rr * 8;
                    const int b = r >> 11;
                    const int s = r & 2047;
                    const size_t di = (((size_t)(b * NH + h) * SEQ) + s) * HD + d;
                    *reinterpret_cast<float2*>(&dst[di]) =
                        make_float2(rr ? v10 : v00, rr ? v11 : v01);
                }
            }
        }
    }
}

// ---------------------------------------------------------------------------
// Tensor-core flash attention.
// QK^T: plain tf32 (Q/K pre-converted to tf32 at staging — zero inner ALU).
// PV:   3xTF32 with V pre-split into hi/lo smem planes (zero inner ALU except
//       P register splits, hoisted over j).
// Softmax in exp2 domain (ex2.approx, log2e folded into scale and mask).
// ---------------------------------------------------------------------------
#define QKS 68   // Qs/Ks/Ps row stride: bank = 4g+c, conflict-free
#define VST 72   // Vh/Vl row stride: bank = 8c+g, conflict-free
#define LOG2E 1.4426950408889634f

__global__ __launch_bounds__(128) void attn_tc(const float* __restrict__ amask)
{
    extern __shared__ float smem[];
    float* Qs = smem;                   // 64*68  (tf32 values)
    float* Ks = Qs + 64 * QKS;          // 64*68  (tf32 values)
    float* Vh = Ks + 64 * QKS;          // 64*72  [key][hd] tf32 hi
    float* Vl = Vh + 64 * VST;          // 64*72  tf32 lo
    float* Ps = Vl + 64 * VST;          // 64*68
    float* Ms = Ps + 64 * QKS;          // SEQ (already scaled by log2e)

    const int bh   = blockIdx.y;
    const int qt   = blockIdx.x;
    const int b    = bh >> 4;
    const int h    = bh & 15;
    const int q0   = qt * 64;
    const int t    = threadIdx.x;
    const int warp = t >> 5;
    const int lane = t & 31;
    const int g    = lane >> 2;
    const int c    = lane & 3;
    const int wm   = warp * 16;

    const float* Qg = g_q + (size_t)bh * SEQ * HD;
    const float* Kg = g_k + (size_t)bh * SEQ * HD;
    const float* Vg = g_v + (size_t)bh * SEQ * HD;

    // Load Q tile (tf32-converted) and mask row (pre-multiplied by log2e)
    for (int idx = t; idx < 1024; idx += 128) {
        int r = idx >> 4, d4 = idx & 15;
        float4 q4 = *reinterpret_cast<const float4*>(&Qg[(q0 + r) * HD + d4 * 4]);
        *reinterpret_cast<float4*>(&Qs[r * QKS + d4 * 4]) =
            make_float4(f2tf32(q4.x), f2tf32(q4.y), f2tf32(q4.z), f2tf32(q4.w));
    }
    for (int i = t; i < SEQ; i += 128) Ms[i] = amask[b * SEQ + i] * LOG2E;

    const int r0 = q0 + wm + g;
    const int r1 = r0 + 8;

    float oacc[8][4];
    #pragma unroll
    for (int j = 0; j < 8; j++)
        #pragma unroll
        for (int q = 0; q < 4; q++) oacc[j][q] = 0.f;
    float m0 = -1e30f, m1 = -1e30f, l0 = 0.f, l1 = 0.f;   // log2 domain

    const int ktiles = qt + 1;
    for (int kt = 0; kt < ktiles; kt++) {
        const int k0 = kt * 64;
        __syncthreads();
        for (int idx = t; idx < 1024; idx += 128) {
            int r = idx >> 4, d4 = idx & 15;
            float4 k4 = *reinterpret_cast<const float4*>(&Kg[(k0 + r) * HD + d4 * 4]);
            *reinterpret_cast<float4*>(&Ks[r * QKS + d4 * 4]) =
                make_float4(f2tf32(k4.x), f2tf32(k4.y), f2tf32(k4.z), f2tf32(k4.w));
            float4 v4 = *reinterpret_cast<const float4*>(&Vg[(k0 + r) * HD + d4 * 4]);
            uint32_t hx, lx, hy, ly, hz, lz, hw, lw;
            splitf(v4.x, hx, lx); splitf(v4.y, hy, ly);
            splitf(v4.z, hz, lz); splitf(v4.w, hw, lw);
            *reinterpret_cast<float4*>(&Vh[r * VST + d4 * 4]) =
                make_float4(__uint_as_float(hx), __uint_as_float(hy),
                            __uint_as_float(hz), __uint_as_float(hw));
            *reinterpret_cast<float4*>(&Vl[r * VST + d4 * 4]) =
                make_float4(__uint_as_float(lx), __uint_as_float(ly),
                            __uint_as_float(lz), __uint_as_float(lw));
        }
        __syncthreads();

        // ---- S = Q K^T (plain tf32, pure LDS+MMA) ----
        float sacc[8][4];
        #pragma unroll
        for (int j = 0; j < 8; j++)
            #pragma unroll
            for (int q = 0; q < 4; q++) sacc[j][q] = 0.f;

        #pragma unroll
        for (int kk = 0; kk < 8; kk++) {
            uint32_t a[4];
            a[0] = __float_as_uint(Qs[(wm + g)     * QKS + kk * 8 + c]);
            a[1] = __float_as_uint(Qs[(wm + g + 8) * QKS + kk * 8 + c]);
            a[2] = __float_as_uint(Qs[(wm + g)     * QKS + kk * 8 + c + 4]);
            a[3] = __float_as_uint(Qs[(wm + g + 8) * QKS + kk * 8 + c + 4]);
            #pragma unroll
            for (int j = 0; j < 8; j++) {
                uint32_t bb[2];
                bb[0] = __float_as_uint(Ks[(j * 8 + g) * QKS + kk * 8 + c]);
                bb[1] = __float_as_uint(Ks[(j * 8 + g) * QKS + kk * 8 + c + 4]);
                mma_tf32(sacc[j], a, bb);
            }
        }

        // ---- masked online softmax (log2 domain) ----
        constexpr float SC  = 0.125f * LOG2E;
        constexpr float NEG = -10000.f * LOG2E;
        #pragma unroll
        for (int j = 0; j < 8; j++) {
            const int col  = k0 + j * 8 + 2 * c;
            const int col1 = col + 1;
            const float msk0 = Ms[col], msk1 = Ms[col1];
            sacc[j][0] = (col  <= r0) ? fmaf(sacc[j][0], SC, msk0) : (NEG + msk0);
            sacc[j][1] = (col1 <= r0) ? fmaf(sacc[j][1], SC, msk1) : (NEG + msk1);
            sacc[j][2] = (col  <= r1) ? fmaf(sacc[j][2], SC, msk0) : (NEG + msk0);
            sacc[j][3] = (col1 <= r1) ? fmaf(sacc[j][3], SC, msk1) : (NEG + msk1);
        }
        float mt0 = -1e30f, mt1 = -1e30f;
        #pragma unroll
        for (int j = 0; j < 8; j++) {
            mt0 = fmaxf(mt0, fmaxf(sacc[j][0], sacc[j][1]));
            mt1 = fmaxf(mt1, fmaxf(sacc[j][2], sacc[j][3]));
        }
        mt0 = fmaxf(mt0, __shfl_xor_sync(0xffffffffu, mt0, 1));
        mt0 = fmaxf(mt0, __shfl_xor_sync(0xffffffffu, mt0, 2));
        mt1 = fmaxf(mt1, __shfl_xor_sync(0xffffffffu, mt1, 1));
        mt1 = fmaxf(mt1, __shfl_xor_sync(0xffffffffu, mt1, 2));
        const float mn0 = fmaxf(m0, mt0), mn1 = fmaxf(m1, mt1);
        const float al0 = fexp2(m0 - mn0), al1 = fexp2(m1 - mn1);
        m0 = mn0; m1 = mn1;

        float ps0 = 0.f, ps1 = 0.f;
        #pragma unroll
        for (int j = 0; j < 8; j++) {
            float p0 = fexp2(sacc[j][0] - mn0);
            float p1 = fexp2(sacc[j][1] - mn0);
            float p2 = fexp2(sacc[j][2] - mn1);
            float p3 = fexp2(sacc[j][3] - mn1);
            ps0 += p0 + p1;
            ps1 += p2 + p3;
            *reinterpret_cast<float2*>(&Ps[(wm + g)     * QKS + j * 8 + 2 * c]) = make_float2(p0, p1);
            *reinterpret_cast<float2*>(&Ps[(wm + g + 8) * QKS + j * 8 + 2 * c]) = make_float2(p2, p3);
        }
        ps0 += __shfl_xor_sync(0xffffffffu, ps0, 1);
        ps0 += __shfl_xor_sync(0xffffffffu, ps0, 2);
        ps1 += __shfl_xor_sync(0xffffffffu, ps1, 1);
        ps1 += __shfl_xor_sync(0xffffffffu, ps1, 2);
        l0 = l0 * al0 + ps0;
        l1 = l1 * al1 + ps1;
        #pragma unroll
        for (int j = 0; j < 8; j++) {
            oacc[j][0] *= al0; oacc[j][1] *= al0;
            oacc[j][2] *= al1; oacc[j][3] *= al1;
        }
        __syncwarp();

        // ---- O += P V (3xTF32; V pre-split in smem, P split per kk) ----
        #pragma unroll
        for (int kk = 0; kk < 8; kk++) {
            uint32_t ph[4], pl[4];
            splitf(Ps[(wm + g)     * QKS + kk * 8 + c],     ph[0], pl[0]);
            splitf(Ps[(wm + g + 8) * QKS + kk * 8 + c],     ph[1], pl[1]);
            splitf(Ps[(wm + g)     * QKS + kk * 8 + c + 4], ph[2], pl[2]);
            splitf(Ps[(wm + g + 8) * QKS + kk * 8 + c + 4], ph[3], pl[3]);
            #pragma unroll
            for (int j = 0; j < 8; j++) {
                uint32_t vh[2], vl[2];
                vh[0] = __float_as_uint(Vh[(kk * 8 + c)     * VST + j * 8 + g]);
                vh[1] = __float_as_uint(Vh[(kk * 8 + c + 4) * VST + j * 8 + g]);
                vl[0] = __float_as_uint(Vl[(kk * 8 + c)     * VST + j * 8 + g]);
                vl[1] = __float_as_uint(Vl[(kk * 8 + c + 4) * VST + j * 8 + g]);
                mma_tf32(oacc[j], ph, vh);
                mma_tf32(oacc[j], ph, vl);
                mma_tf32(oacc[j], pl, vh);
            }
        }
    }

    // Epilogue
    const float inv0 = 1.f / l0, inv1 = 1.f / l1;
    const size_t base0 = ((size_t)(b * SEQ + r0)) * DM + h * HD;
    const size_t base1 = ((size_t)(b * SEQ + r1)) * DM + h * HD;
    #pragma unroll
    for (int j = 0; j < 8; j++) {
        *reinterpret_cast<float2*>(&g_a[base0 + j * 8 + 2 * c]) =
            make_float2(oacc[j][0] * inv0, oacc[j][1] * inv0);
        *reinterpret_cast<float2*>(&g_a[base1 + j * 8 + 2 * c]) =
            make_float2(oacc[j][2] * inv1, oacc[j][3] * inv1);
    }
}

// ---------------------------------------------------------------------------
extern "C" void kernel_launch(void* const* d_in, const int* in_sizes, int n_in,
                              void* d_out, int out_size)
{
    const float* x      = (const float*)d_in[0];
    const float* amask  = (const float*)d_in[1];
    const float* W_attn = (const float*)d_in[2];
    const float* b_attn = (const float*)d_in[3];
    const float* W_proj = (const float*)d_in[4];
    const float* b_proj = (const float*)d_in[5];
    float* out = (float*)d_out;

    dim3 g1(3072 / 128, MTOT / 128);
    gemm_tc<MTOT, 3072, DM, 1, 0><<<g1, 256>>>(x, W_attn, b_attn, out);

    size_t smem = (size_t)(64 * (QKS * 3 + VST * 2) + SEQ) * sizeof(float);  // 97,280 B
    cudaFuncSetAttribute(attn_tc, cudaFuncAttributeMaxDynamicSharedMemorySize, (int)smem);
    attn_tc<<<dim3(SEQ / 64, BH), 128, smem>>>(amask);

    dim3 g2(DM / 128, MTOT / 128);
    gemm_tc<MTOT, DM, DM, 0, 1><<<g2, 256>>>(nullptr, W_proj, b_proj, out);
}

// round 12
// speedup vs baseline: 2.9641x; 1.1269x over previous
#include <cuda_runtime.h>
#include <cstdint>

#define BDIM 4
#define SEQ  2048
#define DM   1024
#define NH   16
#define HD   64
#define BH   (BDIM*NH)     // 64
#define MTOT (BDIM*SEQ)    // 8192

// Static scratch: q/k/v in [B,H,S,hd], merged attn out [B,S,D]
__device__ float g_q[BH * SEQ * HD];
__device__ float g_k[BH * SEQ * HD];
__device__ float g_v[BH * SEQ * HD];
__device__ float g_a[MTOT * DM];

__device__ __forceinline__ float f2tf32(float f) {
    uint32_t u;
    asm("cvt.rna.tf32.f32 %0, %1;" : "=r"(u) : "f"(f));
    return __uint_as_float(u);
}

__device__ __forceinline__ void splitf(float x, uint32_t& h, uint32_t& l) {
    asm("cvt.rna.tf32.f32 %0, %1;" : "=r"(h) : "f"(x));
    float r = x - __uint_as_float(h);
    asm("cvt.rna.tf32.f32 %0, %1;" : "=r"(l) : "f"(r));
}

__device__ __forceinline__ float fexp2(float x) {
    float y;
    asm("ex2.approx.ftz.f32 %0, %1;" : "=f"(y) : "f"(x));
    return y;
}

__device__ __forceinline__ void mma_tf32(float* d, const uint32_t* a, const uint32_t* b) {
    asm volatile(
        "mma.sync.aligned.m16n8k8.row.col.f32.tf32.tf32.f32 "
        "{%0,%1,%2,%3}, {%4,%5,%6,%7}, {%8,%9}, {%0,%1,%2,%3};"
        : "+f"(d[0]), "+f"(d[1]), "+f"(d[2]), "+f"(d[3])
        : "r"(a[0]), "r"(a[1]), "r"(a[2]), "r"(a[3]), "r"(b[0]), "r"(b[1]));
}

// ---------------------------------------------------------------------------
// TF32 GEMM, 64x64 warp tiles: 128 threads, 4 warps in 2x2 over BM=BN=128.
// Fragment reuse 8x on both operands -> 1.0 LDS-wavefront per MMA.
// ---------------------------------------------------------------------------
template<int M, int N, int K, int EPI, int ASRC>
__global__ __launch_bounds__(128) void gemm_tc(const float* __restrict__ A,
                                               const float* __restrict__ B,
                                               const float* __restrict__ bias,
                                               float* __restrict__ C)
{
    constexpr int BM = 128, BN = 128, BK = 16;
    constexpr int AS = 20;
    constexpr int BS = 136;
    __shared__ float As[BM * AS];
    __shared__ float Bs[BK * BS];

    const float* Ap = (ASRC == 1) ? g_a : A;

    const int t    = threadIdx.x;
    const int warp = t >> 5;
    const int lane = t & 31;
    const int wm   = (warp >> 1) * 64;
    const int wn   = (warp & 1) * 64;
    const int g    = lane >> 2;
    const int c    = lane & 3;
    const int row0 = blockIdx.y * BM;
    const int col0 = blockIdx.x * BN;

    const int arow = t >> 2;     // 0..31, +{0,32,64,96}
    const int acv  = t & 3;
    const int brow = t >> 5;     // 0..3, +{0,4,8,12}
    const int bcv  = t & 31;

    float acc[4][8][4];
    #pragma unroll
    for (int i = 0; i < 4; i++)
        #pragma unroll
        for (int j = 0; j < 8; j++)
            #pragma unroll
            for (int q = 0; q < 4; q++) acc[i][j][q] = 0.f;

    for (int k0 = 0; k0 < K; k0 += BK) {
        float4 av[4], bv[4];
        #pragma unroll
        for (int u = 0; u < 4; u++)
            av[u] = *reinterpret_cast<const float4*>(&Ap[(size_t)(row0 + arow + u * 32) * K + k0 + acv * 4]);
        #pragma unroll
        for (int u = 0; u < 4; u++)
            bv[u] = *reinterpret_cast<const float4*>(&B[(size_t)(k0 + brow + u * 4) * N + col0 + bcv * 4]);
        __syncthreads();
        #pragma unroll
        for (int u = 0; u < 4; u++)
            *reinterpret_cast<float4*>(&As[(arow + u * 32) * AS + acv * 4]) =
                make_float4(f2tf32(av[u].x), f2tf32(av[u].y), f2tf32(av[u].z), f2tf32(av[u].w));
        #pragma unroll
        for (int u = 0; u < 4; u++)
            *reinterpret_cast<float4*>(&Bs[(brow + u * 4) * BS + bcv * 4]) =
                make_float4(f2tf32(bv[u].x), f2tf32(bv[u].y), f2tf32(bv[u].z), f2tf32(bv[u].w));
        __syncthreads();

        #pragma unroll
        for (int s = 0; s < 2; s++) {
            const int kk = s * 8 + c;
            uint32_t af[4][4];
            #pragma unroll
            for (int i = 0; i < 4; i++) {
                const int r = wm + i * 16 + g;
                af[i][0] = __float_as_uint(As[r * AS + kk]);
                af[i][1] = __float_as_uint(As[(r + 8) * AS + kk]);
                af[i][2] = __float_as_uint(As[r * AS + kk + 4]);
                af[i][3] = __float_as_uint(As[(r + 8) * AS + kk + 4]);
            }
            #pragma unroll
            for (int j = 0; j < 8; j++) {
                const int col = wn + j * 8 + g;
                uint32_t bf[2];
                bf[0] = __float_as_uint(Bs[kk * BS + col]);
                bf[1] = __float_as_uint(Bs[(kk + 4) * BS + col]);
                #pragma unroll
                for (int i = 0; i < 4; i++)
                    mma_tf32(acc[i][j], af[i], bf);
            }
        }
    }

    #pragma unroll
    for (int i = 0; i < 4; i++) {
        const int r_lo = row0 + wm + i * 16 + g;
        #pragma unroll
        for (int j = 0; j < 8; j++) {
            const int cb = col0 + wn + j * 8 + c * 2;
            float v00 = acc[i][j][0] + bias[cb];
            float v01 = acc[i][j][1] + bias[cb + 1];
            float v10 = acc[i][j][2] + bias[cb];
            float v11 = acc[i][j][3] + bias[cb + 1];
            if (EPI == 0) {
                *reinterpret_cast<float2*>(&C[(size_t)r_lo * N + cb])       = make_float2(v00, v01);
                *reinterpret_cast<float2*>(&C[(size_t)(r_lo + 8) * N + cb]) = make_float2(v10, v11);
            } else {
                const int which = cb >> 10;
                const int dd    = cb & 1023;
                const int h     = dd >> 6;
                const int d     = dd & 63;
                float* dst = (which == 0) ? g_q : (which == 1) ? g_k : g_v;
                #pragma unroll
                for (int rr = 0; rr < 2; rr++) {
                    const int r = r_lo + rr * 8;
                    const int b = r >> 11;
                    const int s = r & 2047;
                    const size_t di = (((size_t)(b * NH + h) * SEQ) + s) * HD + d;
                    *reinterpret_cast<float2*>(&dst[di]) =
                        make_float2(rr ? v10 : v00, rr ? v11 : v01);
                }
            }
        }
    }
}

// ---------------------------------------------------------------------------
// Tensor-core flash attention v3.
// CTA = 128 q rows, 4 warps, warp = 32 q rows (2 m16 tiles).
// Q fragments pre-scaled (0.125*log2e), tf32-converted, held in REGISTERS for
// the whole k-loop (loop-invariant) — S-phase inner loop is pure K-LDS + MMA.
// PV: 3xTF32, V pre-split hi/lo in smem. Softmax in exp2 domain.
// ---------------------------------------------------------------------------
#define QKS 68   // Ps/Ks row stride: bank = 4g+c, conflict-free
#define VST 72   // Vh/Vl row stride: bank = 8c+g, conflict-free
#define LOG2E 1.4426950408889634f

__global__ __launch_bounds__(128, 2) void attn_tc(const float* __restrict__ amask)
{
    extern __shared__ float smem[];
    float* Ps = smem;                   // 128*68 (Q staging in prologue, then P)
    float* Ks = Ps + 128 * QKS;         // 64*68 tf32
    float* Vh = Ks + 64 * QKS;          // 64*72 tf32 hi
    float* Vl = Vh + 64 * VST;          // 64*72 tf32 lo
    float* Ms = Vl + 64 * VST;          // 64 (scaled by log2e)

    const int bh   = blockIdx.y;
    const int qt   = blockIdx.x;
    const int b    = bh >> 4;
    const int h    = bh & 15;
    const int q0   = qt * 128;
    const int t    = threadIdx.x;
    const int warp = t >> 5;
    const int lane = t & 31;
    const int g    = lane >> 2;
    const int c    = lane & 3;
    const int wm   = warp * 32;

    const float* Qg = g_q + (size_t)bh * SEQ * HD;
    const float* Kg = g_k + (size_t)bh * SEQ * HD;
    const float* Vg = g_v + (size_t)bh * SEQ * HD;

    constexpr float SC   = 0.125f * LOG2E;
    constexpr float NEGL = -10000.f * LOG2E;

    // ---- Prologue: stage Q (scaled, tf32) into Ps, lift fragments to regs ----
    for (int idx = t; idx < 2048; idx += 128) {
        int r = idx >> 4, d4 = idx & 15;
        float4 q4 = *reinterpret_cast<const float4*>(&Qg[(q0 + r) * HD + d4 * 4]);
        *reinterpret_cast<float4*>(&Ps[r * QKS + d4 * 4]) =
            make_float4(f2tf32(q4.x * SC), f2tf32(q4.y * SC),
                        f2tf32(q4.z * SC), f2tf32(q4.w * SC));
    }
    __syncthreads();

    uint32_t Qr[2][8][4];
    #pragma unroll
    for (int i = 0; i < 2; i++) {
        const int r = wm + i * 16 + g;
        #pragma unroll
        for (int kk = 0; kk < 8; kk++) {
            Qr[i][kk][0] = __float_as_uint(Ps[r * QKS + kk * 8 + c]);
            Qr[i][kk][1] = __float_as_uint(Ps[(r + 8) * QKS + kk * 8 + c]);
            Qr[i][kk][2] = __float_as_uint(Ps[r * QKS + kk * 8 + c + 4]);
            Qr[i][kk][3] = __float_as_uint(Ps[(r + 8) * QKS + kk * 8 + c + 4]);
        }
    }

    float oacc[2][8][4];
    #pragma unroll
    for (int i = 0; i < 2; i++)
        #pragma unroll
        for (int j = 0; j < 8; j++)
            #pragma unroll
            for (int q = 0; q < 4; q++) oacc[i][j][q] = 0.f;
    float mv[2][2], lv[2][2];
    #pragma unroll
    for (int i = 0; i < 2; i++) {
        mv[i][0] = -1e30f; mv[i][1] = -1e30f;
        lv[i][0] = 0.f;    lv[i][1] = 0.f;
    }

    const int ktiles = 2 * qt + 2;
    for (int kt = 0; kt < ktiles; kt++) {
        const int k0 = kt * 64;
        __syncthreads();
        for (int idx = t; idx < 1024; idx += 128) {
            int r = idx >> 4, d4 = idx & 15;
            float4 k4 = *reinterpret_cast<const float4*>(&Kg[(k0 + r) * HD + d4 * 4]);
            *reinterpret_cast<float4*>(&Ks[r * QKS + d4 * 4]) =
                make_float4(f2tf32(k4.x), f2tf32(k4.y), f2tf32(k4.z), f2tf32(k4.w));
            float4 v4 = *reinterpret_cast<const float4*>(&Vg[(k0 + r) * HD + d4 * 4]);
            uint32_t hx, lx, hy, ly, hz, lz, hw, lw;
            splitf(v4.x, hx, lx); splitf(v4.y, hy, ly);
            splitf(v4.z, hz, lz); splitf(v4.w, hw, lw);
            *reinterpret_cast<float4*>(&Vh[r * VST + d4 * 4]) =
                make_float4(__uint_as_float(hx), __uint_as_float(hy),
                            __uint_as_float(hz), __uint_as_float(hw));
            *reinterpret_cast<float4*>(&Vl[r * VST + d4 * 4]) =
                make_float4(__uint_as_float(lx), __uint_as_float(ly),
                            __uint_as_float(lz), __uint_as_float(lw));
        }
        if (t < 64) Ms[t] = amask[b * SEQ + k0 + t] * LOG2E;
        __syncthreads();

        // ---- S = Q K^T : pure K-LDS + MMA (Q in registers) ----
        float sacc[2][8][4];
        #pragma unroll
        for (int i = 0; i < 2; i++)
            #pragma unroll
            for (int j = 0; j < 8; j++)
                #pragma unroll
                for (int q = 0; q < 4; q++) sacc[i][j][q] = 0.f;

        #pragma unroll
        for (int kk = 0; kk < 8; kk++) {
            #pragma unroll
            for (int j = 0; j < 8; j++) {
                uint32_t bb[2];
                bb[0] = __float_as_uint(Ks[(j * 8 + g) * QKS + kk * 8 + c]);
                bb[1] = __float_as_uint(Ks[(j * 8 + g) * QKS + kk * 8 + c + 4]);
                mma_tf32(sacc[0][j], Qr[0][kk], bb);
                mma_tf32(sacc[1][j], Qr[1][kk], bb);
            }
        }

        // ---- masked online softmax (log2 domain; scale pre-folded into Q) ----
        #pragma unroll
        for (int i = 0; i < 2; i++) {
            const int ra = q0 + wm + i * 16 + g;
            const int rb = ra + 8;
            #pragma unroll
            for (int j = 0; j < 8; j++) {
                const int col  = k0 + j * 8 + 2 * c;
                const float msk0 = Ms[j * 8 + 2 * c];
                const float msk1 = Ms[j * 8 + 2 * c + 1];
                float* s = sacc[i][j];
                s[0] = (col     <= ra) ? s[0] + msk0 : (NEGL + msk0);
                s[1] = (col + 1 <= ra) ? s[1] + msk1 : (NEGL + msk1);
                s[2] = (col     <= rb) ? s[2] + msk0 : (NEGL + msk0);
                s[3] = (col + 1 <= rb) ? s[3] + msk1 : (NEGL + msk1);
            }
            float mt0 = -1e30f, mt1 = -1e30f;
            #pragma unroll
            for (int j = 0; j < 8; j++) {
                mt0 = fmaxf(mt0, fmaxf(sacc[i][j][0], sacc[i][j][1]));
                mt1 = fmaxf(mt1, fmaxf(sacc[i][j][2], sacc[i][j][3]));
            }
            mt0 = fmaxf(mt0, __shfl_xor_sync(0xffffffffu, mt0, 1));
            mt0 = fmaxf(mt0, __shfl_xor_sync(0xffffffffu, mt0, 2));
            mt1 = fmaxf(mt1, __shfl_xor_sync(0xffffffffu, mt1, 1));
            mt1 = fmaxf(mt1, __shfl_xor_sync(0xffffffffu, mt1, 2));
            const float mn0 = fmaxf(mv[i][0], mt0), mn1 = fmaxf(mv[i][1], mt1);
            const float al0 = fexp2(mv[i][0] - mn0), al1 = fexp2(mv[i][1] - mn1);
            mv[i][0] = mn0; mv[i][1] = mn1;

            float ps0 = 0.f, ps1 = 0.f;
            const int pr = wm + i * 16 + g;
            #pragma unroll
            for (int j = 0; j < 8; j++) {
                float p0 = fexp2(sacc[i][j][0] - mn0);
                float p1 = fexp2(sacc[i][j][1] - mn0);
                float p2 = fexp2(sacc[i][j][2] - mn1);
                float p3 = fexp2(sacc[i][j][3] - mn1);
                ps0 += p0 + p1;
                ps1 += p2 + p3;
                *reinterpret_cast<float2*>(&Ps[pr * QKS + j * 8 + 2 * c])       = make_float2(p0, p1);
                *reinterpret_cast<float2*>(&Ps[(pr + 8) * QKS + j * 8 + 2 * c]) = make_float2(p2, p3);
            }
            ps0 += __shfl_xor_sync(0xffffffffu, ps0, 1);
            ps0 += __shfl_xor_sync(0xffffffffu, ps0, 2);
            ps1 += __shfl_xor_sync(0xffffffffu, ps1, 1);
            ps1 += __shfl_xor_sync(0xffffffffu, ps1, 2);
            lv[i][0] = lv[i][0] * al0 + ps0;
            lv[i][1] = lv[i][1] * al1 + ps1;
            #pragma unroll
            for (int j = 0; j < 8; j++) {
                oacc[i][j][0] *= al0; oacc[i][j][1] *= al0;
                oacc[i][j][2] *= al1; oacc[i][j][3] *= al1;
            }
        }
        __syncwarp();

        // ---- O += P V (3xTF32; V pre-split in smem) ----
        #pragma unroll
        for (int kk = 0; kk < 8; kk++) {
            uint32_t ph[2][4], pl[2][4];
            #pragma unroll
            for (int i = 0; i < 2; i++) {
                const int pr = wm + i * 16 + g;
                splitf(Ps[pr * QKS + kk * 8 + c],           ph[i][0], pl[i][0]);
                splitf(Ps[(pr + 8) * QKS + kk * 8 + c],     ph[i][1], pl[i][1]);
                splitf(Ps[pr * QKS + kk * 8 + c + 4],       ph[i][2], pl[i][2]);
                splitf(Ps[(pr + 8) * QKS + kk * 8 + c + 4], ph[i][3], pl[i][3]);
            }
            #pragma unroll
            for (int j = 0; j < 8; j++) {
                uint32_t vh[2], vl[2];
                vh[0] = __float_as_uint(Vh[(kk * 8 + c)     * VST + j * 8 + g]);
                vh[1] = __float_as_uint(Vh[(kk * 8 + c + 4) * VST + j * 8 + g]);
                vl[0] = __float_as_uint(Vl[(kk * 8 + c)     * VST + j * 8 + g]);
                vl[1] = __float_as_uint(Vl[(kk * 8 + c + 4) * VST + j * 8 + g]);
                #pragma unroll
                for (int i = 0; i < 2; i++) {
                    mma_tf32(oacc[i][j], ph[i], vh);
                    mma_tf32(oacc[i][j], ph[i], vl);
                    mma_tf32(oacc[i][j], pl[i], vh);
                }
            }
        }
    }

    // ---- Epilogue: normalize, write merged-head layout [B,S,D] ----
    #pragma unroll
    for (int i = 0; i < 2; i++) {
        const float inv0 = 1.f / lv[i][0], inv1 = 1.f / lv[i][1];
        const int ra = q0 + wm + i * 16 + g;
        const size_t base0 = ((size_t)(b * SEQ + ra)) * DM + h * HD;
        const size_t base1 = ((size_t)(b * SEQ + ra + 8)) * DM + h * HD;
        #pragma unroll
        for (int j = 0; j < 8; j++) {
            *reinterpret_cast<float2*>(&g_a[base0 + j * 8 + 2 * c]) =
                make_float2(oacc[i][j][0] * inv0, oacc[i][j][1] * inv0);
            *reinterpret_cast<float2*>(&g_a[base1 + j * 8 + 2 * c]) =
                make_float2(oacc[i][j][2] * inv1, oacc[i][j][3] * inv1);
        }
    }
}

// ---------------------------------------------------------------------------
extern "C" void kernel_launch(void* const* d_in, const int* in_sizes, int n_in,
                              void* d_out, int out_size)
{
    const float* x      = (const float*)d_in[0];
    const float* amask  = (const float*)d_in[1];
    const float* W_attn = (const float*)d_in[2];
    const float* b_attn = (const float*)d_in[3];
    const float* W_proj = (const float*)d_in[4];
    const float* b_proj = (const float*)d_in[5];
    float* out = (float*)d_out;

    dim3 g1(3072 / 128, MTOT / 128);
    gemm_tc<MTOT, 3072, DM, 1, 0><<<g1, 128>>>(x, W_attn, b_attn, out);

    size_t smem = (size_t)(128 * QKS + 64 * QKS + 2 * 64 * VST + 64) * sizeof(float);  // 89,600 B
    cudaFuncSetAttribute(attn_tc, cudaFuncAttributeMaxDynamicSharedMemorySize, (int)smem);
    attn_tc<<<dim3(SEQ / 128, BH), 128, smem>>>(amask);

    dim3 g2(DM / 128, MTOT / 128);
    gemm_tc<MTOT, DM, DM, 0, 1><<<g2, 128>>>(nullptr, W_proj, b_proj, out);
}

// round 13
// speedup vs baseline: 3.5420x; 1.1950x over previous
#include <cuda_runtime.h>
#include <cstdint>

#define BDIM 4
#define SEQ  2048
#define DM   1024
#define NH   16
#define HD   64
#define BH   (BDIM*NH)     // 64
#define MTOT (BDIM*SEQ)    // 8192

// Static scratch: q/k/v in [B,H,S,hd], merged attn out [B,S,D]
__device__ float g_q[BH * SEQ * HD];
__device__ float g_k[BH * SEQ * HD];
__device__ float g_v[BH * SEQ * HD];
__device__ float g_a[MTOT * DM];

__device__ __forceinline__ float f2tf32(float f) {
    uint32_t u;
    asm("cvt.rna.tf32.f32 %0, %1;" : "=r"(u) : "f"(f));
    return __uint_as_float(u);
}

__device__ __forceinline__ float fexp2(float x) {
    float y;
    asm("ex2.approx.ftz.f32 %0, %1;" : "=f"(y) : "f"(x));
    return y;
}

__device__ __forceinline__ void mma_tf32(float* d, const uint32_t* a, const uint32_t* b) {
    asm volatile(
        "mma.sync.aligned.m16n8k8.row.col.f32.tf32.tf32.f32 "
        "{%0,%1,%2,%3}, {%4,%5,%6,%7}, {%8,%9}, {%0,%1,%2,%3};"
        : "+f"(d[0]), "+f"(d[1]), "+f"(d[2]), "+f"(d[3])
        : "r"(a[0]), "r"(a[1]), "r"(a[2]), "r"(a[3]), "r"(b[0]), "r"(b[1]));
}

// ---------------------------------------------------------------------------
// TF32 GEMM, 64x64 warp tiles (unchanged from R10 — HMMA-throughput-capped).
// ---------------------------------------------------------------------------
template<int M, int N, int K, int EPI, int ASRC>
__global__ __launch_bounds__(128) void gemm_tc(const float* __restrict__ A,
                                               const float* __restrict__ B,
                                               const float* __restrict__ bias,
                                               float* __restrict__ C)
{
    constexpr int BM = 128, BN = 128, BK = 16;
    constexpr int AS = 20;
    constexpr int BS = 136;
    __shared__ float As[BM * AS];
    __shared__ float Bs[BK * BS];

    const float* Ap = (ASRC == 1) ? g_a : A;

    const int t    = threadIdx.x;
    const int warp = t >> 5;
    const int lane = t & 31;
    const int wm   = (warp >> 1) * 64;
    const int wn   = (warp & 1) * 64;
    const int g    = lane >> 2;
    const int c    = lane & 3;
    const int row0 = blockIdx.y * BM;
    const int col0 = blockIdx.x * BN;

    const int arow = t >> 2;
    const int acv  = t & 3;
    const int brow = t >> 5;
    const int bcv  = t & 31;

    float acc[4][8][4];
    #pragma unroll
    for (int i = 0; i < 4; i++)
        #pragma unroll
        for (int j = 0; j < 8; j++)
            #pragma unroll
            for (int q = 0; q < 4; q++) acc[i][j][q] = 0.f;

    for (int k0 = 0; k0 < K; k0 += BK) {
        float4 av[4], bv[4];
        #pragma unroll
        for (int u = 0; u < 4; u++)
            av[u] = *reinterpret_cast<const float4*>(&Ap[(size_t)(row0 + arow + u * 32) * K + k0 + acv * 4]);
        #pragma unroll
        for (int u = 0; u < 4; u++)
            bv[u] = *reinterpret_cast<const float4*>(&B[(size_t)(k0 + brow + u * 4) * N + col0 + bcv * 4]);
        __syncthreads();
        #pragma unroll
        for (int u = 0; u < 4; u++)
            *reinterpret_cast<float4*>(&As[(arow + u * 32) * AS + acv * 4]) =
                make_float4(f2tf32(av[u].x), f2tf32(av[u].y), f2tf32(av[u].z), f2tf32(av[u].w));
        #pragma unroll
        for (int u = 0; u < 4; u++)
            *reinterpret_cast<float4*>(&Bs[(brow + u * 4) * BS + bcv * 4]) =
                make_float4(f2tf32(bv[u].x), f2tf32(bv[u].y), f2tf32(bv[u].z), f2tf32(bv[u].w));
        __syncthreads();

        #pragma unroll
        for (int s = 0; s < 2; s++) {
            const int kk = s * 8 + c;
            uint32_t af[4][4];
            #pragma unroll
            for (int i = 0; i < 4; i++) {
                const int r = wm + i * 16 + g;
                af[i][0] = __float_as_uint(As[r * AS + kk]);
                af[i][1] = __float_as_uint(As[(r + 8) * AS + kk]);
                af[i][2] = __float_as_uint(As[r * AS + kk + 4]);
                af[i][3] = __float_as_uint(As[(r + 8) * AS + kk + 4]);
            }
            #pragma unroll
            for (int j = 0; j < 8; j++) {
                const int col = wn + j * 8 + g;
                uint32_t bf[2];
                bf[0] = __float_as_uint(Bs[kk * BS + col]);
                bf[1] = __float_as_uint(Bs[(kk + 4) * BS + col]);
                #pragma unroll
                for (int i = 0; i < 4; i++)
                    mma_tf32(acc[i][j], af[i], bf);
            }
        }
    }

    #pragma unroll
    for (int i = 0; i < 4; i++) {
        const int r_lo = row0 + wm + i * 16 + g;
        #pragma unroll
        for (int j = 0; j < 8; j++) {
            const int cb = col0 + wn + j * 8 + c * 2;
            float v00 = acc[i][j][0] + bias[cb];
            float v01 = acc[i][j][1] + bias[cb + 1];
            float v10 = acc[i][j][2] + bias[cb];
            float v11 = acc[i][j][3] + bias[cb + 1];
            if (EPI == 0) {
                *reinterpret_cast<float2*>(&C[(size_t)r_lo * N + cb])       = make_float2(v00, v01);
                *reinterpret_cast<float2*>(&C[(size_t)(r_lo + 8) * N + cb]) = make_float2(v10, v11);
            } else {
                const int which = cb >> 10;
                const int dd    = cb & 1023;
                const int h     = dd >> 6;
                const int d     = dd & 63;
                float* dst = (which == 0) ? g_q : (which == 1) ? g_k : g_v;
                #pragma unroll
                for (int rr = 0; rr < 2; rr++) {
                    const int r = r_lo + rr * 8;
                    const int b = r >> 11;
                    const int s = r & 2047;
                    const size_t di = (((size_t)(b * NH + h) * SEQ) + s) * HD + d;
                    *reinterpret_cast<float2*>(&dst[di]) =
                        make_float2(rr ? v10 : v00, rr ? v11 : v01);
                }
            }
        }
    }
}

// ---------------------------------------------------------------------------
// Tensor-core flash attention v4: ALL matmuls plain 1x tf32.
// CTA = 128 q rows, 4 warps, warp = 32 q rows (2 m16 tiles).
// Q frags (pre-scaled by 0.125*log2e, tf32) live in registers for the k-loop.
// K, V converted to tf32 at staging; P tf32-rounded before smem store and l
// accumulated from the rounded values for P/l consistency.
// ---------------------------------------------------------------------------
#define QKS 68   // Ps/Ks row stride: bank = 4g+c, conflict-free
#define VST 72   // Vs row stride: bank = 8c+g, conflict-free
#define LOG2E 1.4426950408889634f

__global__ __launch_bounds__(128, 2) void attn_tc(const float* __restrict__ amask)
{
    extern __shared__ float smem[];
    float* Ps = smem;                   // 128*68 (Q staging in prologue, then P)
    float* Ks = Ps + 128 * QKS;         // 64*68 tf32
    float* Vs = Ks + 64 * QKS;          // 64*72 tf32, [key][hd]
    float* Ms = Vs + 64 * VST;          // 64 (scaled by log2e)

    const int bh   = blockIdx.y;
    const int qt   = blockIdx.x;
    const int b    = bh >> 4;
    const int h    = bh & 15;
    const int q0   = qt * 128;
    const int t    = threadIdx.x;
    const int warp = t >> 5;
    const int lane = t & 31;
    const int g    = lane >> 2;
    const int c    = lane & 3;
    const int wm   = warp * 32;

    const float* Qg = g_q + (size_t)bh * SEQ * HD;
    const float* Kg = g_k + (size_t)bh * SEQ * HD;
    const float* Vg = g_v + (size_t)bh * SEQ * HD;

    constexpr float SC   = 0.125f * LOG2E;
    constexpr float NEGL = -10000.f * LOG2E;

    // ---- Prologue: stage Q (scaled, tf32) into Ps, lift fragments to regs ----
    for (int idx = t; idx < 2048; idx += 128) {
        int r = idx >> 4, d4 = idx & 15;
        float4 q4 = *reinterpret_cast<const float4*>(&Qg[(q0 + r) * HD + d4 * 4]);
        *reinterpret_cast<float4*>(&Ps[r * QKS + d4 * 4]) =
            make_float4(f2tf32(q4.x * SC), f2tf32(q4.y * SC),
                        f2tf32(q4.z * SC), f2tf32(q4.w * SC));
    }
    __syncthreads();

    uint32_t Qr[2][8][4];
    #pragma unroll
    for (int i = 0; i < 2; i++) {
        const int r = wm + i * 16 + g;
        #pragma unroll
        for (int kk = 0; kk < 8; kk++) {
            Qr[i][kk][0] = __float_as_uint(Ps[r * QKS + kk * 8 + c]);
            Qr[i][kk][1] = __float_as_uint(Ps[(r + 8) * QKS + kk * 8 + c]);
            Qr[i][kk][2] = __float_as_uint(Ps[r * QKS + kk * 8 + c + 4]);
            Qr[i][kk][3] = __float_as_uint(Ps[(r + 8) * QKS + kk * 8 + c + 4]);
        }
    }

    float oacc[2][8][4];
    #pragma unroll
    for (int i = 0; i < 2; i++)
        #pragma unroll
        for (int j = 0; j < 8; j++)
            #pragma unroll
            for (int q = 0; q < 4; q++) oacc[i][j][q] = 0.f;
    float mv[2][2], lv[2][2];
    #pragma unroll
    for (int i = 0; i < 2; i++) {
        mv[i][0] = -1e30f; mv[i][1] = -1e30f;
        lv[i][0] = 0.f;    lv[i][1] = 0.f;
    }

    const int ktiles = 2 * qt + 2;
    for (int kt = 0; kt < ktiles; kt++) {
        const int k0 = kt * 64;
        __syncthreads();
        for (int idx = t; idx < 1024; idx += 128) {
            int r = idx >> 4, d4 = idx & 15;
            float4 k4 = *reinterpret_cast<const float4*>(&Kg[(k0 + r) * HD + d4 * 4]);
            *reinterpret_cast<float4*>(&Ks[r * QKS + d4 * 4]) =
                make_float4(f2tf32(k4.x), f2tf32(k4.y), f2tf32(k4.z), f2tf32(k4.w));
            float4 v4 = *reinterpret_cast<const float4*>(&Vg[(k0 + r) * HD + d4 * 4]);
            *reinterpret_cast<float4*>(&Vs[r * VST + d4 * 4]) =
                make_float4(f2tf32(v4.x), f2tf32(v4.y), f2tf32(v4.z), f2tf32(v4.w));
        }
        if (t < 64) Ms[t] = amask[b * SEQ + k0 + t] * LOG2E;
        __syncthreads();

        // ---- S = Q K^T : pure K-LDS + MMA (Q in registers) ----
        float sacc[2][8][4];
        #pragma unroll
        for (int i = 0; i < 2; i++)
            #pragma unroll
            for (int j = 0; j < 8; j++)
                #pragma unroll
                for (int q = 0; q < 4; q++) sacc[i][j][q] = 0.f;

        #pragma unroll
        for (int kk = 0; kk < 8; kk++) {
            #pragma unroll
            for (int j = 0; j < 8; j++) {
                uint32_t bb[2];
                bb[0] = __float_as_uint(Ks[(j * 8 + g) * QKS + kk * 8 + c]);
                bb[1] = __float_as_uint(Ks[(j * 8 + g) * QKS + kk * 8 + c + 4]);
                mma_tf32(sacc[0][j], Qr[0][kk], bb);
                mma_tf32(sacc[1][j], Qr[1][kk], bb);
            }
        }

        // ---- masked online softmax (log2 domain; scale pre-folded into Q) ----
        #pragma unroll
        for (int i = 0; i < 2; i++) {
            const int ra = q0 + wm + i * 16 + g;
            const int rb = ra + 8;
            #pragma unroll
            for (int j = 0; j < 8; j++) {
                const int col  = k0 + j * 8 + 2 * c;
                const float msk0 = Ms[j * 8 + 2 * c];
                const float msk1 = Ms[j * 8 + 2 * c + 1];
                float* s = sacc[i][j];
                s[0] = (col     <= ra) ? s[0] + msk0 : (NEGL + msk0);
                s[1] = (col + 1 <= ra) ? s[1] + msk1 : (NEGL + msk1);
                s[2] = (col     <= rb) ? s[2] + msk0 : (NEGL + msk0);
                s[3] = (col + 1 <= rb) ? s[3] + msk1 : (NEGL + msk1);
            }
            float mt0 = -1e30f, mt1 = -1e30f;
            #pragma unroll
            for (int j = 0; j < 8; j++) {
                mt0 = fmaxf(mt0, fmaxf(sacc[i][j][0], sacc[i][j][1]));
                mt1 = fmaxf(mt1, fmaxf(sacc[i][j][2], sacc[i][j][3]));
            }
            mt0 = fmaxf(mt0, __shfl_xor_sync(0xffffffffu, mt0, 1));
            mt0 = fmaxf(mt0, __shfl_xor_sync(0xffffffffu, mt0, 2));
            mt1 = fmaxf(mt1, __shfl_xor_sync(0xffffffffu, mt1, 1));
            mt1 = fmaxf(mt1, __shfl_xor_sync(0xffffffffu, mt1, 2));
            const float mn0 = fmaxf(mv[i][0], mt0), mn1 = fmaxf(mv[i][1], mt1);
            const float al0 = fexp2(mv[i][0] - mn0), al1 = fexp2(mv[i][1] - mn1);
            mv[i][0] = mn0; mv[i][1] = mn1;

            float ps0 = 0.f, ps1 = 0.f;
            const int pr = wm + i * 16 + g;
            #pragma unroll
            for (int j = 0; j < 8; j++) {
                // tf32-round P, accumulate l from the ROUNDED values (consistency)
                float p0 = f2tf32(fexp2(sacc[i][j][0] - mn0));
                float p1 = f2tf32(fexp2(sacc[i][j][1] - mn0));
                float p2 = f2tf32(fexp2(sacc[i][j][2] - mn1));
                float p3 = f2tf32(fexp2(sacc[i][j][3] - mn1));
                ps0 += p0 + p1;
                ps1 += p2 + p3;
                *reinterpret_cast<float2*>(&Ps[pr * QKS + j * 8 + 2 * c])       = make_float2(p0, p1);
                *reinterpret_cast<float2*>(&Ps[(pr + 8) * QKS + j * 8 + 2 * c]) = make_float2(p2, p3);
            }
            ps0 += __shfl_xor_sync(0xffffffffu, ps0, 1);
            ps0 += __shfl_xor_sync(0xffffffffu, ps0, 2);
            ps1 += __shfl_xor_sync(0xffffffffu, ps1, 1);
            ps1 += __shfl_xor_sync(0xffffffffu, ps1, 2);
            lv[i][0] = lv[i][0] * al0 + ps0;
            lv[i][1] = lv[i][1] * al1 + ps1;
            #pragma unroll
            for (int j = 0; j < 8; j++) {
                oacc[i][j][0] *= al0; oacc[i][j][1] *= al0;
                oacc[i][j][2] *= al1; oacc[i][j][3] *= al1;
            }
        }
        __syncwarp();

        // ---- O += P V : plain 1x tf32, pure LDS + MMA ----
        #pragma unroll
        for (int kk = 0; kk < 8; kk++) {
            uint32_t pf[2][4];
            #pragma unroll
            for (int i = 0; i < 2; i++) {
                const int pr = wm + i * 16 + g;
                pf[i][0] = __float_as_uint(Ps[pr * QKS + kk * 8 + c]);
                pf[i][1] = __float_as_uint(Ps[(pr + 8) * QKS + kk * 8 + c]);
                pf[i][2] = __float_as_uint(Ps[pr * QKS + kk * 8 + c + 4]);
                pf[i][3] = __float_as_uint(Ps[(pr + 8) * QKS + kk * 8 + c + 4]);
            }
            #pragma unroll
            for (int j = 0; j < 8; j++) {
                uint32_t vf[2];
                vf[0] = __float_as_uint(Vs[(kk * 8 + c)     * VST + j * 8 + g]);
                vf[1] = __float_as_uint(Vs[(kk * 8 + c + 4) * VST + j * 8 + g]);
                mma_tf32(oacc[0][j], pf[0], vf);
                mma_tf32(oacc[1][j], pf[1], vf);
            }
        }
    }

    // ---- Epilogue: normalize, write merged-head layout [B,S,D] ----
    #pragma unroll
    for (int i = 0; i < 2; i++) {
        const float inv0 = 1.f / lv[i][0], inv1 = 1.f / lv[i][1];
        const int ra = q0 + wm + i * 16 + g;
        const size_t base0 = ((size_t)(b * SEQ + ra)) * DM + h * HD;
        const size_t base1 = ((size_t)(b * SEQ + ra + 8)) * DM + h * HD;
        #pragma unroll
        for (int j = 0; j < 8; j++) {
            *reinterpret_cast<float2*>(&g_a[base0 + j * 8 + 2 * c]) =
                make_float2(oacc[i][j][0] * inv0, oacc[i][j][1] * inv0);
            *reinterpret_cast<float2*>(&g_a[base1 + j * 8 + 2 * c]) =
                make_float2(oacc[i][j][2] * inv1, oacc[i][j][3] * inv1);
        }
    }
}

// ---------------------------------------------------------------------------
extern "C" void kernel_launch(void* const* d_in, const int* in_sizes, int n_in,
                              void* d_out, int out_size)
{
    const float* x      = (const float*)d_in[0];
    const float* amask  = (const float*)d_in[1];
    const float* W_attn = (const float*)d_in[2];
    const float* b_attn = (const float*)d_in[3];
    const float* W_proj = (const float*)d_in[4];
    const float* b_proj = (const float*)d_in[5];
    float* out = (float*)d_out;

    dim3 g1(3072 / 128, MTOT / 128);
    gemm_tc<MTOT, 3072, DM, 1, 0><<<g1, 128>>>(x, W_attn, b_attn, out);

    size_t smem = (size_t)(128 * QKS + 64 * QKS + 64 * VST + 64) * sizeof(float);  // 70,912 B
    cudaFuncSetAttribute(attn_tc, cudaFuncAttributeMaxDynamicSharedMemorySize, (int)smem);
    attn_tc<<<dim3(SEQ / 128, BH), 128, smem>>>(amask);

    dim3 g2(DM / 128, MTOT / 128);
    gemm_tc<MTOT, DM, DM, 0, 1><<<g2, 128>>>(nullptr, W_proj, b_proj, out);
}

// round 14
// speedup vs baseline: 6.6971x; 1.8908x over previous
#include <cuda_runtime.h>
#include <cuda_fp16.h>
#include <cstdint>

#define BDIM 4
#define SEQ  2048
#define DM   1024
#define NH   16
#define HD   64
#define BH   (BDIM*NH)     // 64
#define MTOT (BDIM*SEQ)    // 8192
#define LOG2E 1.4426950408889634f
#define QSCALE (0.125f * LOG2E)

// Static scratch
__device__ __half   g_xh[MTOT * DM];            // x in fp16
__device__ uint32_t g_wa[(DM/2) * (3*DM)];      // W_attn, k-pair packed half2
__device__ uint32_t g_wp[(DM/2) * DM];          // W_proj,  k-pair packed half2
__device__ __half   g_qh[BH * SEQ * HD];        // q (pre-scaled by QSCALE)
__device__ __half   g_kh[BH * SEQ * HD];
__device__ __half   g_vh[BH * SEQ * HD];
__device__ __half   g_ah[MTOT * DM];            // merged attn out, fp16

__device__ __forceinline__ float fexp2(float x) {
    float y;
    asm("ex2.approx.ftz.f32 %0, %1;" : "=f"(y) : "f"(x));
    return y;
}

__device__ __forceinline__ void mma_f16(float* d, const uint32_t* a, const uint32_t* b) {
    asm volatile(
        "mma.sync.aligned.m16n8k16.row.col.f32.f16.f16.f32 "
        "{%0,%1,%2,%3}, {%4,%5,%6,%7}, {%8,%9}, {%0,%1,%2,%3};"
        : "+f"(d[0]), "+f"(d[1]), "+f"(d[2]), "+f"(d[3])
        : "r"(a[0]), "r"(a[1]), "r"(a[2]), "r"(a[3]), "r"(b[0]), "r"(b[1]));
}

__device__ __forceinline__ uint32_t h2u(__half2 h) { return *reinterpret_cast<uint32_t*>(&h); }

// ---------------------------------------------------------------------------
// One-time packing kernels
// ---------------------------------------------------------------------------
__global__ void pack_x_k(const float* __restrict__ x) {
    int i = blockIdx.x * 256 + threadIdx.x;          // over MTOT*DM/4
    float4 v = reinterpret_cast<const float4*>(x)[i];
    uint2 o = make_uint2(h2u(__floats2half2_rn(v.x, v.y)),
                         h2u(__floats2half2_rn(v.z, v.w)));
    reinterpret_cast<uint2*>(g_xh)[i] = o;
}

__global__ void pack_wa_k(const float* __restrict__ W) {
    const int ND = 3 * DM;
    int idx = blockIdx.x * 256 + threadIdx.x;        // over (DM/2)*ND
    int kp = idx / ND, n = idx - kp * ND;
    g_wa[idx] = h2u(__floats2half2_rn(W[(2*kp)*ND + n], W[(2*kp+1)*ND + n]));
}

__global__ void pack_wp_k(const float* __restrict__ W) {
    const int ND = DM;
    int idx = blockIdx.x * 256 + threadIdx.x;        // over (DM/2)*ND
    int kp = idx / ND, n = idx - kp * ND;
    g_wp[idx] = h2u(__floats2half2_rn(W[(2*kp)*ND + n], W[(2*kp+1)*ND + n]));
}

// ---------------------------------------------------------------------------
// FP16 GEMM (m16n8k16, fp32 accum): C[M,N] = A @ B + bias
// 128 threads, 4 warps in 2x2, warp tile 64x64, BM=BN=128, BK=32.
// ASEL: 0 = g_xh, 1 = g_ah.  BSEL: 0 = g_wa, 1 = g_wp.
// EPI: 0 = fp32 store to C.  1 = scatter fp16 into g_qh/g_kh/g_vh (q scaled).
// ---------------------------------------------------------------------------
template<int M, int N, int K, int EPI, int ASEL, int BSEL>
__global__ __launch_bounds__(128) void gemm_h(const float* __restrict__ bias,
                                              float* __restrict__ C)
{
    constexpr int BK  = 32;
    constexpr int ASU = 20;    // uints per A row (16 data + 4 pad): 20g+c perm mod 32
    constexpr int BSU = 136;   // uints per B kp-row (128 + 8 pad): 8c+g perm
    __shared__ uint32_t As[128 * ASU];   // 10.2 KB
    __shared__ uint32_t Bs[16 * BSU];    // 8.7 KB

    const __half*    A  = (ASEL == 0) ? g_xh : g_ah;
    const uint32_t*  Bp = (BSEL == 0) ? g_wa : g_wp;

    const int t    = threadIdx.x;
    const int warp = t >> 5;
    const int lane = t & 31;
    const int wm   = (warp >> 1) * 64;
    const int wn   = (warp & 1) * 64;
    const int g    = lane >> 2;
    const int c    = lane & 3;
    const int row0 = blockIdx.y * 128;
    const int col0 = blockIdx.x * 128;

    float acc[4][8][4];
    #pragma unroll
    for (int i = 0; i < 4; i++)
        #pragma unroll
        for (int j = 0; j < 8; j++)
            #pragma unroll
            for (int q = 0; q < 4; q++) acc[i][j][q] = 0.f;

    for (int k0 = 0; k0 < K; k0 += BK) {
        // stage A: 128 rows x 16 uints = 512 uint4
        uint4 av[4], bv[4];
        #pragma unroll
        for (int u = 0; u < 4; u++) {
            int idx = t + u * 128;
            int row = idx >> 2, q4 = idx & 3;
            av[u] = *reinterpret_cast<const uint4*>(&A[(size_t)(row0 + row) * K + k0 + q4 * 8]);
        }
        // stage B: 16 kp-rows x 128 uints = 512 uint4
        #pragma unroll
        for (int u = 0; u < 4; u++) {
            int idx = t + u * 128;
            int kp = idx >> 5, n4 = idx & 31;
            bv[u] = *reinterpret_cast<const uint4*>(&Bp[(size_t)(k0 / 2 + kp) * N + col0 + n4 * 4]);
        }
        __syncthreads();
        #pragma unroll
        for (int u = 0; u < 4; u++) {
            int idx = t + u * 128;
            int row = idx >> 2, q4 = idx & 3;
            *reinterpret_cast<uint4*>(&As[row * ASU + q4 * 4]) = av[u];
        }
        #pragma unroll
        for (int u = 0; u < 4; u++) {
            int idx = t + u * 128;
            int kp = idx >> 5, n4 = idx & 31;
            *reinterpret_cast<uint4*>(&Bs[kp * BSU + n4 * 4]) = bv[u];
        }
        __syncthreads();

        #pragma unroll
        for (int s = 0; s < 2; s++) {           // two k16 steps per BK=32
            const int kb = s * 8;               // pair-index base
            uint32_t af[4][4];
            #pragma unroll
            for (int i = 0; i < 4; i++) {
                const int r = wm + i * 16 + g;
                af[i][0] = As[r * ASU + kb + c];
                af[i][1] = As[(r + 8) * ASU + kb + c];
                af[i][2] = As[r * ASU + kb + c + 4];
                af[i][3] = As[(r + 8) * ASU + kb + c + 4];
            }
            #pragma unroll
            for (int j = 0; j < 8; j++) {
                const int col = wn + j * 8 + g;
                uint32_t bf[2];
                bf[0] = Bs[(kb + c) * BSU + col];
                bf[1] = Bs[(kb + c + 4) * BSU + col];
                #pragma unroll
                for (int i = 0; i < 4; i++)
                    mma_f16(acc[i][j], af[i], bf);
            }
        }
    }

    // Epilogue. frag: c0 (g,2c), c1 (g,2c+1), c2 (g+8,2c), c3 (g+8,2c+1)
    #pragma unroll
    for (int i = 0; i < 4; i++) {
        const int r_lo = row0 + wm + i * 16 + g;
        #pragma unroll
        for (int j = 0; j < 8; j++) {
            const int cb = col0 + wn + j * 8 + c * 2;
            float v00 = acc[i][j][0] + bias[cb];
            float v01 = acc[i][j][1] + bias[cb + 1];
            float v10 = acc[i][j][2] + bias[cb];
            float v11 = acc[i][j][3] + bias[cb + 1];
            if (EPI == 0) {
                *reinterpret_cast<float2*>(&C[(size_t)r_lo * N + cb])       = make_float2(v00, v01);
                *reinterpret_cast<float2*>(&C[(size_t)(r_lo + 8) * N + cb]) = make_float2(v10, v11);
            } else {
                const int which = cb >> 10;        // 0:q 1:k 2:v
                const int dd    = cb & 1023;
                const int h     = dd >> 6;
                const int d     = dd & 63;
                __half* dst = (which == 0) ? g_qh : (which == 1) ? g_kh : g_vh;
                if (which == 0) { v00 *= QSCALE; v01 *= QSCALE; v10 *= QSCALE; v11 *= QSCALE; }
                #pragma unroll
                for (int rr = 0; rr < 2; rr++) {
                    const int r = r_lo + rr * 8;
                    const int b = r >> 11;
                    const int s = r & 2047;
                    const size_t di = (((size_t)(b * NH + h) * SEQ) + s) * HD + d;
                    __half2 hh = __floats2half2_rn(rr ? v10 : v00, rr ? v11 : v01);
                    *reinterpret_cast<uint32_t*>(&dst[di]) = h2u(hh);
                }
            }
        }
    }
}

// ---------------------------------------------------------------------------
// FP16 tensor-core flash attention (m16n8k16).
// CTA = 128 q rows, 4 warps, warp = 32 q rows (2 m16 tiles).
// Q frags loaded once from gmem into registers (pre-scaled fp16).
// K/V staged as packed half2 uints; P packed half2 in smem; softmax fp32.
// ---------------------------------------------------------------------------
#define KSU 36   // Ks row stride (uints): bank 4g+c, conflict-free
#define VSU 72   // Vs kp-row stride: bank 8c+g, conflict-free
#define PSU 36   // Ps row stride

__global__ __launch_bounds__(128, 2) void attn_h(const float* __restrict__ amask)
{
    __shared__ uint32_t Ks[64 * KSU];    // [key][hd_pair]
    __shared__ uint32_t Vs[32 * VSU];    // [key_pair][hd]
    __shared__ uint32_t Ps[128 * PSU];   // [q_row][key_pair]
    __shared__ float    Ms[64];          // mask (scaled by log2e)

    const int bh   = blockIdx.y;
    const int qt   = blockIdx.x;
    const int b    = bh >> 4;
    const int h    = bh & 15;
    const int q0   = qt * 128;
    const int t    = threadIdx.x;
    const int warp = t >> 5;
    const int lane = t & 31;
    const int g    = lane >> 2;
    const int c    = lane & 3;
    const int wm   = warp * 32;

    const uint32_t* Qu = reinterpret_cast<const uint32_t*>(g_qh) + (size_t)bh * SEQ * 32;
    const uint32_t* Ku = reinterpret_cast<const uint32_t*>(g_kh) + (size_t)bh * SEQ * 32;
    const uint32_t* Vu = reinterpret_cast<const uint32_t*>(g_vh) + (size_t)bh * SEQ * 32;

    constexpr float NEGL = -10000.f * LOG2E;

    // ---- Q fragments: straight from gmem (k-loop invariant) ----
    uint32_t Qr[2][4][4];
    #pragma unroll
    for (int i = 0; i < 2; i++) {
        const int r = q0 + wm + i * 16 + g;
        #pragma unroll
        for (int kk = 0; kk < 4; kk++) {
            Qr[i][kk][0] = Qu[r * 32 + kk * 8 + c];
            Qr[i][kk][1] = Qu[(r + 8) * 32 + kk * 8 + c];
            Qr[i][kk][2] = Qu[r * 32 + kk * 8 + c + 4];
            Qr[i][kk][3] = Qu[(r + 8) * 32 + kk * 8 + c + 4];
        }
    }

    float oacc[2][8][4];
    #pragma unroll
    for (int i = 0; i < 2; i++)
        #pragma unroll
        for (int j = 0; j < 8; j++)
            #pragma unroll
            for (int q = 0; q < 4; q++) oacc[i][j][q] = 0.f;
    float mv[2][2], lv[2][2];
    #pragma unroll
    for (int i = 0; i < 2; i++) {
        mv[i][0] = -1e30f; mv[i][1] = -1e30f;
        lv[i][0] = 0.f;    lv[i][1] = 0.f;
    }

    const int ktiles = 2 * qt + 2;
    for (int kt = 0; kt < ktiles; kt++) {
        const int k0 = kt * 64;
        __syncthreads();
        // K: 64 rows x 32 uints = 512 uint4
        #pragma unroll
        for (int u = 0; u < 4; u++) {
            int idx = t + u * 128;
            int row = idx >> 3, q4 = idx & 7;
            uint4 kv = *reinterpret_cast<const uint4*>(&Ku[(size_t)(k0 + row) * 32 + q4 * 4]);
            *reinterpret_cast<uint4*>(&Ks[row * KSU + q4 * 4]) = kv;
        }
        // V: interleave key-row pairs -> Vs[kp][hd]
        #pragma unroll
        for (int u = 0; u < 2; u++) {
            int idx = t + u * 128;
            int kp = idx >> 3, ub = idx & 7;
            uint4 lo = *reinterpret_cast<const uint4*>(&Vu[(size_t)(k0 + 2 * kp) * 32 + ub * 4]);
            uint4 hi = *reinterpret_cast<const uint4*>(&Vu[(size_t)(k0 + 2 * kp + 1) * 32 + ub * 4]);
            uint4 o0, o1;
            o0.x = __byte_perm(lo.x, hi.x, 0x5410); o0.y = __byte_perm(lo.x, hi.x, 0x7632);
            o0.z = __byte_perm(lo.y, hi.y, 0x5410); o0.w = __byte_perm(lo.y, hi.y, 0x7632);
            o1.x = __byte_perm(lo.z, hi.z, 0x5410); o1.y = __byte_perm(lo.z, hi.z, 0x7632);
            o1.z = __byte_perm(lo.w, hi.w, 0x5410); o1.w = __byte_perm(lo.w, hi.w, 0x7632);
            *reinterpret_cast<uint4*>(&Vs[kp * VSU + ub * 8])     = o0;
            *reinterpret_cast<uint4*>(&Vs[kp * VSU + ub * 8 + 4]) = o1;
        }
        if (t < 64) Ms[t] = amask[b * SEQ + k0 + t] * LOG2E;
        __syncthreads();

        // ---- S = Q K^T ----
        float sacc[2][8][4];
        #pragma unroll
        for (int i = 0; i < 2; i++)
            #pragma unroll
            for (int j = 0; j < 8; j++)
                #pragma unroll
                for (int q = 0; q < 4; q++) sacc[i][j][q] = 0.f;

        #pragma unroll
        for (int kk = 0; kk < 4; kk++) {
            #pragma unroll
            for (int j = 0; j < 8; j++) {
                uint32_t bb[2];
                bb[0] = Ks[(j * 8 + g) * KSU + kk * 8 + c];
                bb[1] = Ks[(j * 8 + g) * KSU + kk * 8 + c + 4];
                mma_f16(sacc[0][j], Qr[0][kk], bb);
                mma_f16(sacc[1][j], Qr[1][kk], bb);
            }
        }

        // ---- masked online softmax (log2 domain; scale folded into Q) ----
        #pragma unroll
        for (int i = 0; i < 2; i++) {
            const int ra = q0 + wm + i * 16 + g;
            const int rb = ra + 8;
            #pragma unroll
            for (int j = 0; j < 8; j++) {
                const int col  = k0 + j * 8 + 2 * c;
                const float msk0 = Ms[j * 8 + 2 * c];
                const float msk1 = Ms[j * 8 + 2 * c + 1];
                float* s = sacc[i][j];
                s[0] = (col     <= ra) ? s[0] + msk0 : (NEGL + msk0);
                s[1] = (col + 1 <= ra) ? s[1] + msk1 : (NEGL + msk1);
                s[2] = (col     <= rb) ? s[2] + msk0 : (NEGL + msk0);
                s[3] = (col + 1 <= rb) ? s[3] + msk1 : (NEGL + msk1);
            }
            float mt0 = -1e30f, mt1 = -1e30f;
            #pragma unroll
            for (int j = 0; j < 8; j++) {
                mt0 = fmaxf(mt0, fmaxf(sacc[i][j][0], sacc[i][j][1]));
                mt1 = fmaxf(mt1, fmaxf(sacc[i][j][2], sacc[i][j][3]));
            }
            mt0 = fmaxf(mt0, __shfl_xor_sync(0xffffffffu, mt0, 1));
            mt0 = fmaxf(mt0, __shfl_xor_sync(0xffffffffu, mt0, 2));
            mt1 = fmaxf(mt1, __shfl_xor_sync(0xffffffffu, mt1, 1));
            mt1 = fmaxf(mt1, __shfl_xor_sync(0xffffffffu, mt1, 2));
            const float mn0 = fmaxf(mv[i][0], mt0), mn1 = fmaxf(mv[i][1], mt1);
            const float al0 = fexp2(mv[i][0] - mn0), al1 = fexp2(mv[i][1] - mn1);
            mv[i][0] = mn0; mv[i][1] = mn1;

            float ps0 = 0.f, ps1 = 0.f;
            const int pr = wm + i * 16 + g;
            #pragma unroll
            for (int j = 0; j < 8; j++) {
                float p0 = fexp2(sacc[i][j][0] - mn0);
                float p1 = fexp2(sacc[i][j][1] - mn0);
                float p2 = fexp2(sacc[i][j][2] - mn1);
                float p3 = fexp2(sacc[i][j][3] - mn1);
                __half2 hp0 = __floats2half2_rn(p0, p1);
                __half2 hp1 = __floats2half2_rn(p2, p3);
                // accumulate l from the ROUNDED P for consistency
                float2 f0 = __half22float2(hp0);
                float2 f1 = __half22float2(hp1);
                ps0 += f0.x + f0.y;
                ps1 += f1.x + f1.y;
                Ps[pr * PSU + j * 4 + c]       = h2u(hp0);
                Ps[(pr + 8) * PSU + j * 4 + c] = h2u(hp1);
            }
            ps0 += __shfl_xor_sync(0xffffffffu, ps0, 1);
            ps0 += __shfl_xor_sync(0xffffffffu, ps0, 2);
            ps1 += __shfl_xor_sync(0xffffffffu, ps1, 1);
            ps1 += __shfl_xor_sync(0xffffffffu, ps1, 2);
            lv[i][0] = lv[i][0] * al0 + ps0;
            lv[i][1] = lv[i][1] * al1 + ps1;
            #pragma unroll
            for (int j = 0; j < 8; j++) {
                oacc[i][j][0] *= al0; oacc[i][j][1] *= al0;
                oacc[i][j][2] *= al1; oacc[i][j][3] *= al1;
            }
        }
        __syncwarp();

        // ---- O += P V ----
        #pragma unroll
        for (int kk = 0; kk < 4; kk++) {
            uint32_t pf[2][4];
            #pragma unroll
            for (int i = 0; i < 2; i++) {
                const int pr = wm + i * 16 + g;
                pf[i][0] = Ps[pr * PSU + kk * 8 + c];
                pf[i][1] = Ps[(pr + 8) * PSU + kk * 8 + c];
                pf[i][2] = Ps[pr * PSU + kk * 8 + c + 4];
                pf[i][3] = Ps[(pr + 8) * PSU + kk * 8 + c + 4];
            }
            #pragma unroll
            for (int j = 0; j < 8; j++) {
                uint32_t vf[2];
                vf[0] = Vs[(kk * 8 + c) * VSU + j * 8 + g];
                vf[1] = Vs[(kk * 8 + c + 4) * VSU + j * 8 + g];
                mma_f16(oacc[0][j], pf[0], vf);
                mma_f16(oacc[1][j], pf[1], vf);
            }
        }
    }

    // ---- Epilogue: normalize, pack fp16, write merged-head [B,S,D] ----
    uint32_t* Au = reinterpret_cast<uint32_t*>(g_ah);
    #pragma unroll
    for (int i = 0; i < 2; i++) {
        const float inv0 = 1.f / lv[i][0], inv1 = 1.f / lv[i][1];
        const int ra = q0 + wm + i * 16 + g;
        const size_t base0 = ((size_t)(b * SEQ + ra)) * 512 + h * 32;      // uint units (DM/2)
        const size_t base1 = ((size_t)(b * SEQ + ra + 8)) * 512 + h * 32;
        #pragma unroll
        for (int j = 0; j < 8; j++) {
            Au[base0 + j * 4 + c] = h2u(__floats2half2_rn(oacc[i][j][0] * inv0, oacc[i][j][1] * inv0));
            Au[base1 + j * 4 + c] = h2u(__floats2half2_rn(oacc[i][j][2] * inv1, oacc[i][j][3] * inv1));
        }
    }
}

// ---------------------------------------------------------------------------
extern "C" void kernel_launch(void* const* d_in, const int* in_sizes, int n_in,
                              void* d_out, int out_size)
{
    const float* x      = (const float*)d_in[0];
    const float* amask  = (const float*)d_in[1];
    const float* W_attn = (const float*)d_in[2];
    const float* b_attn = (const float*)d_in[3];
    const float* W_proj = (const float*)d_in[4];
    const float* b_proj = (const float*)d_in[5];
    float* out = (float*)d_out;

    // 0) pack inputs/weights to fp16
    pack_x_k <<<(MTOT * DM / 4) / 256, 256>>>(x);
    pack_wa_k<<<((DM / 2) * (3 * DM)) / 256, 256>>>(W_attn);
    pack_wp_k<<<((DM / 2) * DM) / 256, 256>>>(W_proj);

    // 1) QKV GEMM (fp16 m16n8k16) with head-split fp16 scatter epilogue
    dim3 g1(3072 / 128, MTOT / 128);
    gemm_h<MTOT, 3*DM, DM, 1, 0, 0><<<g1, 128>>>(b_attn, nullptr);

    // 2) Attention (fp16 m16n8k16)
    attn_h<<<dim3(SEQ / 128, BH), 128>>>(amask);

    // 3) Output projection (fp16), fp32 output
    dim3 g2(DM / 128, MTOT / 128);
    gemm_h<MTOT, DM, DM, 0, 1, 1><<<g2, 128>>>(b_proj, out);
}